// round 4
// baseline (speedup 1.0000x reference)
#include <cuda_runtime.h>
#include <cuda_bf16.h>
#include <math_constants.h>
#include <cstdint>

#define DDIM    512
#define N_ROWS  16384
#define K_CODES 8192

#define BM      128            // rows per CTA (grid = 128 CTAs, single wave)
#define BN      256            // codes per tile
#define BKH     32             // D-chunk in halves per pipeline stage
#define NTILE   (K_CODES / BN)       // 32
#define GTOT    (K_CODES / BN * (DDIM / BKH))  // 512 B-chunks total
#define MAXCAND 16

// ---- smem layout (bytes) ----
#define A_ROWSTR   1040        // 512 halves + 8 pad halves (260 u32, %32=4 -> conflict-free)
#define OFF_A      0
#define A_BYTES    (BM * A_ROWSTR)            // 133120
#define B_ROWSTR   80                          // 32 halves + 8 pad halves (20 u32)
#define B_STAGE_B  (BN * B_ROWSTR)             // 20480
#define OFF_B      (A_BYTES)                   // 133120
#define OFF_ROWMAX (OFF_B + 3 * B_STAGE_B)     // 194560
#define OFF_MARGIN (OFF_ROWMAX + BM * 4)       // 195072
#define OFF_CCNT   (OFF_MARGIN + BM * 4)       // 195584
#define OFF_CAND   (OFF_CCNT + BM * 4)         // 196096
#define SMEM_TOTAL (OFF_CAND + BM * MAXCAND * 4) // 204288

// ---- device scratch (allocation-free) ----
__device__ __nv_bfloat16 g_xb[(size_t)N_ROWS * DDIM];
__device__ __nv_bfloat16 g_eb[(size_t)K_CODES * DDIM];
__device__ __align__(16) float g_bias[K_CODES];   // -0.5*||e||^2
__device__ float g_xnorm[N_ROWS];
__device__ int   g_emax2;                          // max ||e||^2 (float bits, positive)
__device__ int   g_cand[(size_t)N_ROWS * MAXCAND];
__device__ int   g_ccnt[N_ROWS];
__device__ int   g_ind[N_ROWS];

// ---------------------------------------------------------------------------
__device__ __forceinline__ uint32_t smem_u32(const void* p) {
    uint32_t a;
    asm("{ .reg .u64 t; cvta.to.shared.u64 t, %1; cvt.u32.u64 %0, t; }" : "=r"(a) : "l"(p));
    return a;
}
__device__ __forceinline__ void cp16(uint32_t dst, const void* src) {
    asm volatile("cp.async.cg.shared.global [%0], [%1], 16;" :: "r"(dst), "l"(src) : "memory");
}
#define CP_COMMIT() asm volatile("cp.async.commit_group;" ::: "memory")
#define CP_WAIT2()  asm volatile("cp.async.wait_group 2;" ::: "memory")

__device__ __forceinline__ void mma_bf16(float* d, const uint32_t* a, const uint32_t* b) {
    asm volatile(
        "mma.sync.aligned.m16n8k16.row.col.f32.bf16.bf16.f32 "
        "{%0,%1,%2,%3}, {%4,%5,%6,%7}, {%8,%9}, {%0,%1,%2,%3};"
        : "+f"(d[0]), "+f"(d[1]), "+f"(d[2]), "+f"(d[3])
        : "r"(a[0]), "r"(a[1]), "r"(a[2]), "r"(a[3]), "r"(b[0]), "r"(b[1]));
}

// order-preserving float <-> uint encoding for atomicMax
__device__ __forceinline__ uint32_t fenc(float f) {
    uint32_t u = __float_as_uint(f);
    return (u & 0x80000000u) ? ~u : (u | 0x80000000u);
}
__device__ __forceinline__ float fdec(uint32_t u) {
    return __uint_as_float((u & 0x80000000u) ? (u ^ 0x80000000u) : ~u);
}

// ---------------------------------------------------------------------------
// Convert x -> bf16, ||x|| per row.  One warp per row.
// ---------------------------------------------------------------------------
__global__ void conv_x_kernel(const float* __restrict__ x) {
    int row = (blockIdx.x * blockDim.x + threadIdx.x) >> 5;
    int lane = threadIdx.x & 31;
    if (row >= N_ROWS) return;
    const float4* src = reinterpret_cast<const float4*>(x + (size_t)row * DDIM);
    uint4* dst = reinterpret_cast<uint4*>(g_xb + (size_t)row * DDIM);
    float s = 0.f;
#pragma unroll
    for (int j = 0; j < 2; j++) {
        __nv_bfloat162 h[4];
        float4 v0 = src[lane * 4 + j * 2];
        float4 v1 = src[lane * 4 + j * 2 + 1];
        s += v0.x*v0.x + v0.y*v0.y + v0.z*v0.z + v0.w*v0.w;
        s += v1.x*v1.x + v1.y*v1.y + v1.z*v1.z + v1.w*v1.w;
        h[0] = __nv_bfloat162(__float2bfloat16_rn(v0.x), __float2bfloat16_rn(v0.y));
        h[1] = __nv_bfloat162(__float2bfloat16_rn(v0.z), __float2bfloat16_rn(v0.w));
        h[2] = __nv_bfloat162(__float2bfloat16_rn(v1.x), __float2bfloat16_rn(v1.y));
        h[3] = __nv_bfloat162(__float2bfloat16_rn(v1.z), __float2bfloat16_rn(v1.w));
        dst[lane * 2 + j] = *reinterpret_cast<uint4*>(h);
    }
#pragma unroll
    for (int off = 16; off; off >>= 1) s += __shfl_xor_sync(0xFFFFFFFFu, s, off);
    if (lane == 0) g_xnorm[row] = sqrtf(s);
}

__global__ void conv_e_kernel(const float* __restrict__ e) {
    int row = (blockIdx.x * blockDim.x + threadIdx.x) >> 5;
    int lane = threadIdx.x & 31;
    if (row >= K_CODES) return;
    const float4* src = reinterpret_cast<const float4*>(e + (size_t)row * DDIM);
    uint4* dst = reinterpret_cast<uint4*>(g_eb + (size_t)row * DDIM);
    float s = 0.f;
#pragma unroll
    for (int j = 0; j < 2; j++) {
        __nv_bfloat162 h[4];
        float4 v0 = src[lane * 4 + j * 2];
        float4 v1 = src[lane * 4 + j * 2 + 1];
        s += v0.x*v0.x + v0.y*v0.y + v0.z*v0.z + v0.w*v0.w;
        s += v1.x*v1.x + v1.y*v1.y + v1.z*v1.z + v1.w*v1.w;
        h[0] = __nv_bfloat162(__float2bfloat16_rn(v0.x), __float2bfloat16_rn(v0.y));
        h[1] = __nv_bfloat162(__float2bfloat16_rn(v0.z), __float2bfloat16_rn(v0.w));
        h[2] = __nv_bfloat162(__float2bfloat16_rn(v1.x), __float2bfloat16_rn(v1.y));
        h[3] = __nv_bfloat162(__float2bfloat16_rn(v1.z), __float2bfloat16_rn(v1.w));
        dst[lane * 2 + j] = *reinterpret_cast<uint4*>(h);
    }
#pragma unroll
    for (int off = 16; off; off >>= 1) s += __shfl_xor_sync(0xFFFFFFFFu, s, off);
    if (lane == 0) {
        g_bias[row] = -0.5f * s;
        atomicMax(&g_emax2, __float_as_int(s));   // positive floats: int order OK
    }
}

// ---------------------------------------------------------------------------
// Fused kernel: x-tile resident, stream codebook, running-max + candidates.
// 256 threads = 8 warps (2m x 4n); warp tile 64x64; CTA tile 128 x 256/tile.
// ---------------------------------------------------------------------------
extern __shared__ char smem_g[];

__device__ __forceinline__ void issue_b(uint32_t smb, int gch, int tid) {
    const int kt = gch >> 4;
    const int d0 = (gch & 15) * BKH;
    const int k0 = kt * BN;
    const uint32_t st = smb + OFF_B + (gch % 3) * B_STAGE_B;
#pragma unroll
    for (int it = 0; it < 4; it++) {       // 256 rows x 4x16B
        int i = tid + it * 256;
        int r = i >> 2, c = i & 3;
        cp16(st + r * B_ROWSTR + c * 16,
             g_eb + (size_t)(k0 + r) * DDIM + d0 + c * 8);
    }
}

__global__ __launch_bounds__(256, 1) void fused_kernel() {
    const int tid = threadIdx.x;
    const int lane = tid & 31;
    const int wid = tid >> 5;
    const int wm = wid >> 2;            // 0..1
    const int wn = wid & 3;             // 0..3
    const int g = lane >> 2;            // 0..7
    const int q = lane & 3;             // 0..3
    const int row0 = blockIdx.x * BM;
    const uint32_t smb = smem_u32(smem_g);

    uint32_t* rowmax = reinterpret_cast<uint32_t*>(smem_g + OFF_ROWMAX);
    float*    margin = reinterpret_cast<float*>(smem_g + OFF_MARGIN);
    int*      ccnt   = reinterpret_cast<int*>(smem_g + OFF_CCNT);
    int*      cand   = reinterpret_cast<int*>(smem_g + OFF_CAND);

    // init per-row state
    const float emax = sqrtf(__int_as_float(g_emax2));
    for (int r = tid; r < BM; r += 256) {
        rowmax[r] = 0u;                       // < fenc(any float)
        ccnt[r] = 0;
        margin[r] = 0.02f * g_xnorm[row0 + r] * emax + 0.5f;
    }

    // load resident A tile (128 rows x 1024B) via cp.async
#pragma unroll
    for (int it = 0; it < 32; it++) {         // 8192 x 16B / 256 thr
        int i = tid + it * 256;
        int r = i >> 6, c = i & 63;
        cp16(smb + OFF_A + r * A_ROWSTR + c * 16,
             g_xb + (size_t)(row0 + r) * DDIM + c * 8);
    }
    CP_COMMIT();

    issue_b(smb, 0, tid); CP_COMMIT();
    issue_b(smb, 1, tid); CP_COMMIT();

    const uint32_t* sa = reinterpret_cast<const uint32_t*>(smem_g + OFF_A);

    float acc[4][8][4];
#pragma unroll
    for (int mt = 0; mt < 4; mt++)
#pragma unroll
        for (int nt = 0; nt < 8; nt++)
#pragma unroll
            for (int c = 0; c < 4; c++) acc[mt][nt][c] = 0.f;

    for (int t = 0; t < NTILE; t++) {
        const int col0 = t * BN;

        for (int ch = 0; ch < 16; ch++) {
            const int gch = t * 16 + ch;
            if (gch + 2 < GTOT) issue_b(smb, gch + 2, tid);
            CP_COMMIT();
            CP_WAIT2();
            __syncthreads();

            const uint32_t* sb = reinterpret_cast<const uint32_t*>(
                smem_g + OFF_B + (gch % 3) * B_STAGE_B);
            const int ach = ch * 16;          // u32 offset of this D-chunk in A

#pragma unroll
            for (int s = 0; s < 2; s++) {
                const int s8 = s * 8;
                uint32_t a[4][4], b[8][2];
#pragma unroll
                for (int mt = 0; mt < 4; mt++) {
                    int r = wm * 64 + mt * 16 + g;
                    a[mt][0] = sa[r * 260 + ach + q + s8];
                    a[mt][1] = sa[(r + 8) * 260 + ach + q + s8];
                    a[mt][2] = sa[r * 260 + ach + q + 4 + s8];
                    a[mt][3] = sa[(r + 8) * 260 + ach + q + 4 + s8];
                }
#pragma unroll
                for (int nt = 0; nt < 8; nt++) {
                    int n = wn * 64 + nt * 8 + g;
                    b[nt][0] = sb[n * 20 + q + s8];
                    b[nt][1] = sb[n * 20 + q + 4 + s8];
                }
#pragma unroll
                for (int mt = 0; mt < 4; mt++)
#pragma unroll
                    for (int nt = 0; nt < 8; nt++)
                        mma_bf16(acc[mt][nt], a[mt], b[nt]);
            }
            __syncthreads();
        }

        // ---- tile epilogue: running max + candidate collection ----
        float bcol[8][2];
#pragma unroll
        for (int nt = 0; nt < 8; nt++) {
            int c = col0 + wn * 64 + nt * 8 + q * 2;
            bcol[nt][0] = __ldg(&g_bias[c]);
            bcol[nt][1] = __ldg(&g_bias[c + 1]);
        }
        // phase 1: per-row max
#pragma unroll
        for (int mt = 0; mt < 4; mt++) {
            int r1 = wm * 64 + mt * 16 + g;
            float m1 = -CUDART_INF_F, m2 = -CUDART_INF_F;
#pragma unroll
            for (int nt = 0; nt < 8; nt++) {
                m1 = fmaxf(m1, fmaxf(acc[mt][nt][0] + bcol[nt][0], acc[mt][nt][1] + bcol[nt][1]));
                m2 = fmaxf(m2, fmaxf(acc[mt][nt][2] + bcol[nt][0], acc[mt][nt][3] + bcol[nt][1]));
            }
            atomicMax(&rowmax[r1], fenc(m1));
            atomicMax(&rowmax[r1 + 8], fenc(m2));
        }
        __syncthreads();
        // phase 2: candidates (running-max threshold => superset of final set)
#pragma unroll
        for (int mt = 0; mt < 4; mt++) {
            int r1 = wm * 64 + mt * 16 + g;
            int r2 = r1 + 8;
            float thr1 = fdec(rowmax[r1]) - margin[r1];
            float thr2 = fdec(rowmax[r2]) - margin[r2];
#pragma unroll
            for (int nt = 0; nt < 8; nt++) {
                int c = col0 + wn * 64 + nt * 8 + q * 2;
#pragma unroll
                for (int cc = 0; cc < 2; cc++) {
                    if (acc[mt][nt][cc] + bcol[nt][cc] >= thr1) {
                        int p = atomicAdd(&ccnt[r1], 1);
                        if (p < MAXCAND) cand[r1 * MAXCAND + p] = c + cc;
                    }
                    if (acc[mt][nt][2 + cc] + bcol[nt][cc] >= thr2) {
                        int p = atomicAdd(&ccnt[r2], 1);
                        if (p < MAXCAND) cand[r2 * MAXCAND + p] = c + cc;
                    }
                    acc[mt][nt][cc] = 0.f;
                    acc[mt][nt][2 + cc] = 0.f;
                }
            }
        }
        __syncthreads();
    }

    // flush candidates to global
    for (int r = tid; r < BM; r += 256) {
        int n = ccnt[r];
        g_ccnt[row0 + r] = n;
        int nn = n < MAXCAND ? n : MAXCAND;
        for (int i = 0; i < nn; i++) g_cand[(size_t)(row0 + r) * MAXCAND + i] = cand[r * MAXCAND + i];
    }
}

// ---------------------------------------------------------------------------
// Select: exact fp32 rescore of candidates (warp per row); overflow -> full scan.
// ---------------------------------------------------------------------------
__global__ __launch_bounds__(256) void select_kernel(const float* __restrict__ x,
                                                     const float* __restrict__ embed) {
    const int row = blockIdx.x * 8 + (threadIdx.x >> 5);
    const int lane = threadIdx.x & 31;
    if (row >= N_ROWS) return;

    const float4* x4 = reinterpret_cast<const float4*>(x + (size_t)row * DDIM);
    float4 xv[4];
#pragma unroll
    for (int j = 0; j < 4; j++) xv[j] = x4[lane + 32 * j];

    const int n = g_ccnt[row];
    float best = -CUDART_INF_F;
    int bi = K_CODES;

    if (n <= MAXCAND) {
        for (int ci = 0; ci < n; ci++) {
            int k = g_cand[(size_t)row * MAXCAND + ci];
            const float4* e4 = reinterpret_cast<const float4*>(embed + (size_t)k * DDIM);
            float s = 0.f;
#pragma unroll
            for (int j = 0; j < 4; j++) {
                float4 ev = e4[lane + 32 * j];
                s += xv[j].x * ev.x + xv[j].y * ev.y + xv[j].z * ev.z + xv[j].w * ev.w;
            }
#pragma unroll
            for (int off = 16; off; off >>= 1) s += __shfl_xor_sync(0xFFFFFFFFu, s, off);
            float v = s + g_bias[k];
            if (v > best || (v == best && k < bi)) { best = v; bi = k; }
        }
        if (lane == 0) g_ind[row] = bi;
    } else {
        // overflow: exact scan, lane-parallel over codes
        for (int k = lane; k < K_CODES; k += 32) {
            const float4* e4 = reinterpret_cast<const float4*>(embed + (size_t)k * DDIM);
            float s = 0.f;
            for (int j = 0; j < DDIM / 4; j++) {
                float4 ev = e4[j];
                float4 xw = x4[j];
                s += xw.x * ev.x + xw.y * ev.y + xw.z * ev.z + xw.w * ev.w;
            }
            float v = s + g_bias[k];
            if (v > best || (v == best && k < bi)) { best = v; bi = k; }
        }
#pragma unroll
        for (int off = 16; off; off >>= 1) {
            float ov = __shfl_xor_sync(0xFFFFFFFFu, best, off);
            int   oi = __shfl_xor_sync(0xFFFFFFFFu, bi, off);
            if (ov > best || (ov == best && oi < bi)) { best = ov; bi = oi; }
        }
        if (lane == 0) g_ind[row] = bi;
    }
}

// ---------------------------------------------------------------------------
__global__ void gather_kernel(const float* __restrict__ embed,
                              float* __restrict__ out, int write_ind) {
    int nrow = blockIdx.x;
    int idx = g_ind[nrow];
    const float4* src = reinterpret_cast<const float4*>(embed + (size_t)idx * DDIM);
    float4*       dst = reinterpret_cast<float4*>(out + (size_t)nrow * DDIM);
    for (int i = threadIdx.x; i < DDIM / 4; i += blockDim.x) dst[i] = src[i];
    if (write_ind && threadIdx.x == 0) out[(size_t)N_ROWS * DDIM + nrow] = (float)idx;
}

// ---------------------------------------------------------------------------
extern "C" void kernel_launch(void* const* d_in, const int* in_sizes, int n_in,
                              void* d_out, int out_size) {
    const float* x     = (const float*)d_in[0];
    const float* embed = (const float*)d_in[1];
    float* out = (float*)d_out;
    (void)in_sizes; (void)n_in;
    int write_ind = (out_size >= N_ROWS * DDIM + N_ROWS) ? 1 : 0;

    cudaFuncSetAttribute(fused_kernel, cudaFuncAttributeMaxDynamicSharedMemorySize, SMEM_TOTAL);

    conv_x_kernel<<<N_ROWS / 8, 256>>>(x);
    conv_e_kernel<<<K_CODES / 8, 256>>>(embed);
    fused_kernel<<<N_ROWS / BM, 256, SMEM_TOTAL>>>();
    select_kernel<<<N_ROWS / 8, 256>>>(x, embed);
    gather_kernel<<<N_ROWS, 128>>>(embed, out, write_ind);
}

// round 5
// speedup vs baseline: 39.8986x; 39.8986x over previous
#include <cuda_runtime.h>
#include <cuda_bf16.h>
#include <math_constants.h>
#include <cstdint>

#define DDIM    512
#define N_ROWS  16384
#define K_CODES 8192

// ---- GEMM tiling (round-3 proven shape) ----
#define BM      128
#define BN      256
#define BKH     32
#define NCHUNK  (DDIM / BKH)  // 16
#define ROWSTR_B 80           // 32 halves + pad (20 u32)
#define STAGE_B ((BM + BN) * ROWSTR_B)   // 30720
#define NSTAGE  3
#define SMEM_GEMM (NSTAGE * STAGE_B)     // 92160

#define MAXC    256

// ---- device scratch (allocation-free) ----
__device__ __nv_bfloat16 g_xb[(size_t)N_ROWS * DDIM];
__device__ __nv_bfloat16 g_eb[(size_t)K_CODES * DDIM];
__device__ __align__(16) float g_bias[K_CODES];     // -0.5*||e||^2
__device__ float g_xnorm[N_ROWS];
__device__ int   g_emax2;                 // max ||e||^2 (float bits, >=0) — idempotent across replays
__device__ int   g_cidx[(size_t)N_ROWS * MAXC];
__device__ float g_csc[(size_t)N_ROWS * MAXC];
__device__ int   g_ccnt[N_ROWS];
__device__ int   g_ind[N_ROWS];

// ---------------------------------------------------------------------------
__device__ __forceinline__ uint32_t smem_u32(const void* p) {
    uint32_t a;
    asm("{ .reg .u64 t; cvta.to.shared.u64 t, %1; cvt.u32.u64 %0, t; }" : "=r"(a) : "l"(p));
    return a;
}
__device__ __forceinline__ void cp16(uint32_t dst, const void* src) {
    asm volatile("cp.async.cg.shared.global [%0], [%1], 16;" :: "r"(dst), "l"(src) : "memory");
}
#define CP_COMMIT() asm volatile("cp.async.commit_group;" ::: "memory")
#define CP_WAIT2()  asm volatile("cp.async.wait_group 2;" ::: "memory")

__device__ __forceinline__ void mma_bf16(float* d, const uint32_t* a, const uint32_t* b) {
    asm volatile(
        "mma.sync.aligned.m16n8k16.row.col.f32.bf16.bf16.f32 "
        "{%0,%1,%2,%3}, {%4,%5,%6,%7}, {%8,%9}, {%0,%1,%2,%3};"
        : "+f"(d[0]), "+f"(d[1]), "+f"(d[2]), "+f"(d[3])
        : "r"(a[0]), "r"(a[1]), "r"(a[2]), "r"(a[3]), "r"(b[0]), "r"(b[1]));
}

// order-preserving float<->uint for atomicMax
__device__ __forceinline__ uint32_t fenc(float f) {
    uint32_t u = __float_as_uint(f);
    return (u & 0x80000000u) ? ~u : (u | 0x80000000u);
}
__device__ __forceinline__ float fdec(uint32_t u) {
    return __uint_as_float((u & 0x80000000u) ? (u ^ 0x80000000u) : ~u);
}

// ---------------------------------------------------------------------------
// conv_x: fp32 -> bf16, ||x||, and zero g_ccnt (graph-replay safe). Warp/row.
// ---------------------------------------------------------------------------
__global__ void conv_x_kernel(const float* __restrict__ x) {
    int row = (blockIdx.x * blockDim.x + threadIdx.x) >> 5;
    int lane = threadIdx.x & 31;
    if (row >= N_ROWS) return;
    const float4* src = reinterpret_cast<const float4*>(x + (size_t)row * DDIM);
    uint4* dst = reinterpret_cast<uint4*>(g_xb + (size_t)row * DDIM);
    float s = 0.f;
#pragma unroll
    for (int j = 0; j < 2; j++) {
        __nv_bfloat162 h[4];
        float4 v0 = src[lane * 4 + j * 2];
        float4 v1 = src[lane * 4 + j * 2 + 1];
        s += v0.x*v0.x + v0.y*v0.y + v0.z*v0.z + v0.w*v0.w;
        s += v1.x*v1.x + v1.y*v1.y + v1.z*v1.z + v1.w*v1.w;
        h[0] = __nv_bfloat162(__float2bfloat16_rn(v0.x), __float2bfloat16_rn(v0.y));
        h[1] = __nv_bfloat162(__float2bfloat16_rn(v0.z), __float2bfloat16_rn(v0.w));
        h[2] = __nv_bfloat162(__float2bfloat16_rn(v1.x), __float2bfloat16_rn(v1.y));
        h[3] = __nv_bfloat162(__float2bfloat16_rn(v1.z), __float2bfloat16_rn(v1.w));
        dst[lane * 2 + j] = *reinterpret_cast<uint4*>(h);
    }
#pragma unroll
    for (int off = 16; off; off >>= 1) s += __shfl_xor_sync(0xFFFFFFFFu, s, off);
    if (lane == 0) { g_xnorm[row] = sqrtf(s); g_ccnt[row] = 0; }
}

__global__ void conv_e_kernel(const float* __restrict__ e) {
    int row = (blockIdx.x * blockDim.x + threadIdx.x) >> 5;
    int lane = threadIdx.x & 31;
    if (row >= K_CODES) return;
    const float4* src = reinterpret_cast<const float4*>(e + (size_t)row * DDIM);
    uint4* dst = reinterpret_cast<uint4*>(g_eb + (size_t)row * DDIM);
    float s = 0.f;
#pragma unroll
    for (int j = 0; j < 2; j++) {
        __nv_bfloat162 h[4];
        float4 v0 = src[lane * 4 + j * 2];
        float4 v1 = src[lane * 4 + j * 2 + 1];
        s += v0.x*v0.x + v0.y*v0.y + v0.z*v0.z + v0.w*v0.w;
        s += v1.x*v1.x + v1.y*v1.y + v1.z*v1.z + v1.w*v1.w;
        h[0] = __nv_bfloat162(__float2bfloat16_rn(v0.x), __float2bfloat16_rn(v0.y));
        h[1] = __nv_bfloat162(__float2bfloat16_rn(v0.z), __float2bfloat16_rn(v0.w));
        h[2] = __nv_bfloat162(__float2bfloat16_rn(v1.x), __float2bfloat16_rn(v1.y));
        h[3] = __nv_bfloat162(__float2bfloat16_rn(v1.z), __float2bfloat16_rn(v1.w));
        dst[lane * 2 + j] = *reinterpret_cast<uint4*>(h);
    }
#pragma unroll
    for (int off = 16; off; off >>= 1) s += __shfl_xor_sync(0xFFFFFFFFu, s, off);
    if (lane == 0) {
        g_bias[row] = -0.5f * s;
        atomicMax(&g_emax2, __float_as_int(s));
    }
}

// ---------------------------------------------------------------------------
// GEMM (round-3 structure) + candidate epilogue AFTER the mainloop.
// grid (K/BN, N/BM); 8 warps (2m x 4n), warp tile 64x64.
// ---------------------------------------------------------------------------
extern __shared__ char smem_g[];

__device__ __forceinline__ void gemm_issue(uint32_t smb, int stage, int row0, int col0,
                                           int chunk, int tid) {
    const int d0 = chunk * BKH;
    const uint32_t st = smb + stage * STAGE_B;
#pragma unroll
    for (int it = 0; it < 6; it++) {
        int i = tid + it * 256;
        int r = i >> 2, c = i & 3;
        if (r < BM) {
            cp16(st + r * ROWSTR_B + c * 16, g_xb + (size_t)(row0 + r) * DDIM + d0 + c * 8);
        } else {
            int r2 = r - BM;
            cp16(st + BM * ROWSTR_B + r2 * ROWSTR_B + c * 16,
                 g_eb + (size_t)(col0 + r2) * DDIM + d0 + c * 8);
        }
    }
}

__global__ __launch_bounds__(256, 1) void gemm_kernel() {
    const int tid = threadIdx.x;
    const int lane = tid & 31;
    const int wid = tid >> 5;
    const int wm = wid >> 2;
    const int wn = wid & 3;
    const int g = lane >> 2;
    const int q = lane & 3;
    const int col0 = blockIdx.x * BN;
    const int row0 = blockIdx.y * BM;
    const uint32_t smb = smem_u32(smem_g);

    float acc[4][8][4];
#pragma unroll
    for (int mt = 0; mt < 4; mt++)
#pragma unroll
        for (int nt = 0; nt < 8; nt++)
#pragma unroll
            for (int c = 0; c < 4; c++) acc[mt][nt][c] = 0.f;

    gemm_issue(smb, 0, row0, col0, 0, tid); CP_COMMIT();
    gemm_issue(smb, 1, row0, col0, 1, tid); CP_COMMIT();

    for (int ch = 0; ch < NCHUNK; ch++) {
        if (ch + 2 < NCHUNK) gemm_issue(smb, (ch + 2) % NSTAGE, row0, col0, ch + 2, tid);
        CP_COMMIT();
        CP_WAIT2();
        __syncthreads();

        const uint32_t* sa = reinterpret_cast<const uint32_t*>(smem_g + (ch % NSTAGE) * STAGE_B);
        const uint32_t* sb = sa + BM * (ROWSTR_B / 4);

#pragma unroll
        for (int s = 0; s < 2; s++) {
            const int s8 = s * 8;
            uint32_t a[4][4], b[8][2];
#pragma unroll
            for (int mt = 0; mt < 4; mt++) {
                int r = wm * 64 + mt * 16 + g;
                a[mt][0] = sa[r * 20 + q + s8];
                a[mt][1] = sa[(r + 8) * 20 + q + s8];
                a[mt][2] = sa[r * 20 + q + 4 + s8];
                a[mt][3] = sa[(r + 8) * 20 + q + 4 + s8];
            }
#pragma unroll
            for (int nt = 0; nt < 8; nt++) {
                int n = wn * 64 + nt * 8 + g;
                b[nt][0] = sb[n * 20 + q + s8];
                b[nt][1] = sb[n * 20 + q + 4 + s8];
            }
#pragma unroll
            for (int mt = 0; mt < 4; mt++)
#pragma unroll
                for (int nt = 0; nt < 8; nt++)
                    mma_bf16(acc[mt][nt], a[mt], b[nt]);
        }
        __syncthreads();
    }

    // ================= candidate epilogue (once per CTA) =================
    uint32_t* rowmax_sm = reinterpret_cast<uint32_t*>(smem_g);   // reuse stage smem
    for (int i = tid; i < BM; i += 256) rowmax_sm[i] = 0u;
    __syncthreads();

    // add bias -> acc holds full scores
    float bcol[8][2];
#pragma unroll
    for (int nt = 0; nt < 8; nt++) {
        int c = col0 + wn * 64 + nt * 8 + q * 2;
        bcol[nt][0] = __ldg(&g_bias[c]);
        bcol[nt][1] = __ldg(&g_bias[c + 1]);
    }
#pragma unroll
    for (int mt = 0; mt < 4; mt++)
#pragma unroll
        for (int nt = 0; nt < 8; nt++) {
            acc[mt][nt][0] += bcol[nt][0];
            acc[mt][nt][1] += bcol[nt][1];
            acc[mt][nt][2] += bcol[nt][0];
            acc[mt][nt][3] += bcol[nt][1];
        }

    // per-row tile-local max: thread-local -> shuffle across q -> smem across wn
#pragma unroll
    for (int mt = 0; mt < 4; mt++) {
        float m1 = -CUDART_INF_F, m2 = -CUDART_INF_F;
#pragma unroll
        for (int nt = 0; nt < 8; nt++) {
            m1 = fmaxf(m1, fmaxf(acc[mt][nt][0], acc[mt][nt][1]));
            m2 = fmaxf(m2, fmaxf(acc[mt][nt][2], acc[mt][nt][3]));
        }
        m1 = fmaxf(m1, __shfl_xor_sync(0xFFFFFFFFu, m1, 1));
        m1 = fmaxf(m1, __shfl_xor_sync(0xFFFFFFFFu, m1, 2));
        m2 = fmaxf(m2, __shfl_xor_sync(0xFFFFFFFFu, m2, 1));
        m2 = fmaxf(m2, __shfl_xor_sync(0xFFFFFFFFu, m2, 2));
        if (q == 0) {
            atomicMax(&rowmax_sm[wm * 64 + mt * 16 + g], fenc(m1));
            atomicMax(&rowmax_sm[wm * 64 + mt * 16 + g + 8], fenc(m2));
        }
    }
    __syncthreads();

    const float emax = sqrtf(__int_as_float(g_emax2));
#pragma unroll
    for (int mt = 0; mt < 4; mt++) {
        int lr1 = wm * 64 + mt * 16 + g;
        int lr2 = lr1 + 8;
        int r1 = row0 + lr1, r2 = row0 + lr2;
        float thr1 = fdec(rowmax_sm[lr1]) - (0.02f * g_xnorm[r1] * emax + 0.5f);
        float thr2 = fdec(rowmax_sm[lr2]) - (0.02f * g_xnorm[r2] * emax + 0.5f);
#pragma unroll
        for (int nt = 0; nt < 8; nt++) {
            int c = col0 + wn * 64 + nt * 8 + q * 2;
#pragma unroll
            for (int cc = 0; cc < 2; cc++) {
                float s1 = acc[mt][nt][cc];
                if (s1 >= thr1) {
                    int p = atomicAdd(&g_ccnt[r1], 1);
                    if (p < MAXC) {
                        g_cidx[(size_t)r1 * MAXC + p] = c + cc;
                        g_csc[(size_t)r1 * MAXC + p] = s1;
                    }
                }
                float s2 = acc[mt][nt][2 + cc];
                if (s2 >= thr2) {
                    int p = atomicAdd(&g_ccnt[r2], 1);
                    if (p < MAXC) {
                        g_cidx[(size_t)r2 * MAXC + p] = c + cc;
                        g_csc[(size_t)r2 * MAXC + p] = s2;
                    }
                }
            }
        }
    }
}

// ---------------------------------------------------------------------------
// Select: warp per row. Candidate-max -> exact fp32 rescore within margin.
// ---------------------------------------------------------------------------
__global__ __launch_bounds__(256) void select_kernel(const float* __restrict__ x,
                                                     const float* __restrict__ embed) {
    const int row = blockIdx.x * 8 + (threadIdx.x >> 5);
    const int lane = threadIdx.x & 31;
    if (row >= N_ROWS) return;

    const float4* x4 = reinterpret_cast<const float4*>(x + (size_t)row * DDIM);
    float4 xv[4];
#pragma unroll
    for (int j = 0; j < 4; j++) xv[j] = x4[lane + 32 * j];

    const int n = g_ccnt[row];
    float best = -CUDART_INF_F;
    int bi = K_CODES;

    if (n <= MAXC) {
        // candidate max (== global approx max: every tile's max is a candidate)
        float cmax = -CUDART_INF_F;
        for (int i = lane; i < n; i += 32) cmax = fmaxf(cmax, g_csc[(size_t)row * MAXC + i]);
#pragma unroll
        for (int off = 16; off; off >>= 1) cmax = fmaxf(cmax, __shfl_xor_sync(0xFFFFFFFFu, cmax, off));
        const float thr = cmax - (0.02f * g_xnorm[row] * sqrtf(__int_as_float(g_emax2)) + 0.5f);

        for (int ci = 0; ci < n; ci++) {
            float asc = g_csc[(size_t)row * MAXC + ci];   // broadcast load
            if (asc < thr) continue;
            int k = g_cidx[(size_t)row * MAXC + ci];
            const float4* e4 = reinterpret_cast<const float4*>(embed + (size_t)k * DDIM);
            float s = 0.f;
#pragma unroll
            for (int j = 0; j < 4; j++) {
                float4 ev = e4[lane + 32 * j];
                s += xv[j].x * ev.x + xv[j].y * ev.y + xv[j].z * ev.z + xv[j].w * ev.w;
            }
#pragma unroll
            for (int off = 16; off; off >>= 1) s += __shfl_xor_sync(0xFFFFFFFFu, s, off);
            float v = s + g_bias[k];
            if (v > best || (v == best && k < bi)) { best = v; bi = k; }
        }
        if (lane == 0) g_ind[row] = bi;
    } else {
        // overflow fallback: exact full scan
        for (int k = lane; k < K_CODES; k += 32) {
            const float4* e4 = reinterpret_cast<const float4*>(embed + (size_t)k * DDIM);
            float s = 0.f;
            for (int j = 0; j < DDIM / 4; j++) {
                float4 ev = e4[j];
                float4 xw = x4[j];
                s += xw.x * ev.x + xw.y * ev.y + xw.z * ev.z + xw.w * ev.w;
            }
            float v = s + g_bias[k];
            if (v > best || (v == best && k < bi)) { best = v; bi = k; }
        }
#pragma unroll
        for (int off = 16; off; off >>= 1) {
            float ov = __shfl_xor_sync(0xFFFFFFFFu, best, off);
            int   oi = __shfl_xor_sync(0xFFFFFFFFu, bi, off);
            if (ov > best || (ov == best && oi < bi)) { best = ov; bi = oi; }
        }
        if (lane == 0) g_ind[row] = bi;
    }
}

// ---------------------------------------------------------------------------
__global__ void gather_kernel(const float* __restrict__ embed,
                              float* __restrict__ out, int write_ind) {
    int nrow = blockIdx.x;
    int idx = g_ind[nrow];
    const float4* src = reinterpret_cast<const float4*>(embed + (size_t)idx * DDIM);
    float4*       dst = reinterpret_cast<float4*>(out + (size_t)nrow * DDIM);
    for (int i = threadIdx.x; i < DDIM / 4; i += blockDim.x) dst[i] = src[i];
    if (write_ind && threadIdx.x == 0) out[(size_t)N_ROWS * DDIM + nrow] = (float)idx;
}

// ---------------------------------------------------------------------------
extern "C" void kernel_launch(void* const* d_in, const int* in_sizes, int n_in,
                              void* d_out, int out_size) {
    const float* x     = (const float*)d_in[0];
    const float* embed = (const float*)d_in[1];
    float* out = (float*)d_out;
    (void)in_sizes; (void)n_in;
    int write_ind = (out_size >= N_ROWS * DDIM + N_ROWS) ? 1 : 0;

    cudaFuncSetAttribute(gemm_kernel, cudaFuncAttributeMaxDynamicSharedMemorySize, SMEM_GEMM);

    conv_x_kernel<<<N_ROWS / 8, 256>>>(x);
    conv_e_kernel<<<K_CODES / 8, 256>>>(embed);
    gemm_kernel<<<dim3(K_CODES / BN, N_ROWS / BM), 256, SMEM_GEMM>>>();
    select_kernel<<<N_ROWS / 8, 256>>>(x, embed);
    gather_kernel<<<N_ROWS, 128>>>(embed, out, write_ind);
}

// round 6
// speedup vs baseline: 47.1212x; 1.1810x over previous
#include <cuda_runtime.h>
#include <cuda_bf16.h>
#include <math_constants.h>
#include <cstdint>

#define DDIM    512
#define N_ROWS  16384
#define K_CODES 8192

// ---- GEMM tiling (round-3 proven shape) ----
#define BM      128
#define BN      256
#define BKH     32
#define NCHUNK  (DDIM / BKH)  // 16
#define ROWSTR_B 80           // 32 halves + pad (20 u32)
#define STAGE_B ((BM + BN) * ROWSTR_B)   // 30720
#define NSTAGE  3
#define SMEM_GEMM (NSTAGE * STAGE_B)     // 92160 (>= 64KB scores + 1KB bias)

#define MAXC    256

// ---- device scratch (allocation-free) ----
__device__ __nv_bfloat16 g_xb[(size_t)N_ROWS * DDIM];
__device__ __nv_bfloat16 g_eb[(size_t)K_CODES * DDIM];
__device__ __align__(16) float g_bias[K_CODES];     // -0.5*||e||^2
__device__ float g_xnorm[N_ROWS];
__device__ int   g_emax2;                 // max ||e||^2 (float bits) — idempotent across replays
__device__ uint32_t g_rowmax[N_ROWS];     // fenc-encoded running approx max
__device__ int   g_cidx[(size_t)N_ROWS * MAXC];
__device__ float g_csc[(size_t)N_ROWS * MAXC];
__device__ int   g_ccnt[N_ROWS];

// ---------------------------------------------------------------------------
__device__ __forceinline__ uint32_t smem_u32(const void* p) {
    uint32_t a;
    asm("{ .reg .u64 t; cvta.to.shared.u64 t, %1; cvt.u32.u64 %0, t; }" : "=r"(a) : "l"(p));
    return a;
}
__device__ __forceinline__ void cp16(uint32_t dst, const void* src) {
    asm volatile("cp.async.cg.shared.global [%0], [%1], 16;" :: "r"(dst), "l"(src) : "memory");
}
#define CP_COMMIT() asm volatile("cp.async.commit_group;" ::: "memory")
#define CP_WAIT2()  asm volatile("cp.async.wait_group 2;" ::: "memory")

__device__ __forceinline__ void mma_bf16(float* d, const uint32_t* a, const uint32_t* b) {
    asm volatile(
        "mma.sync.aligned.m16n8k16.row.col.f32.bf16.bf16.f32 "
        "{%0,%1,%2,%3}, {%4,%5,%6,%7}, {%8,%9}, {%0,%1,%2,%3};"
        : "+f"(d[0]), "+f"(d[1]), "+f"(d[2]), "+f"(d[3])
        : "r"(a[0]), "r"(a[1]), "r"(a[2]), "r"(a[3]), "r"(b[0]), "r"(b[1]));
}

// order-preserving float<->uint for atomicMax
__device__ __forceinline__ uint32_t fenc(float f) {
    uint32_t u = __float_as_uint(f);
    return (u & 0x80000000u) ? ~u : (u | 0x80000000u);
}
__device__ __forceinline__ float fdec(uint32_t u) {
    return __uint_as_float((u & 0x80000000u) ? (u ^ 0x80000000u) : ~u);
}

// ---------------------------------------------------------------------------
// conv_x: fp32 -> bf16, ||x||, reset per-row state (graph-replay safe).
// ---------------------------------------------------------------------------
__global__ void conv_x_kernel(const float* __restrict__ x) {
    int row = (blockIdx.x * blockDim.x + threadIdx.x) >> 5;
    int lane = threadIdx.x & 31;
    if (row >= N_ROWS) return;
    const float4* src = reinterpret_cast<const float4*>(x + (size_t)row * DDIM);
    uint4* dst = reinterpret_cast<uint4*>(g_xb + (size_t)row * DDIM);
    float s = 0.f;
#pragma unroll
    for (int j = 0; j < 2; j++) {
        __nv_bfloat162 h[4];
        float4 v0 = src[lane * 4 + j * 2];
        float4 v1 = src[lane * 4 + j * 2 + 1];
        s += v0.x*v0.x + v0.y*v0.y + v0.z*v0.z + v0.w*v0.w;
        s += v1.x*v1.x + v1.y*v1.y + v1.z*v1.z + v1.w*v1.w;
        h[0] = __nv_bfloat162(__float2bfloat16_rn(v0.x), __float2bfloat16_rn(v0.y));
        h[1] = __nv_bfloat162(__float2bfloat16_rn(v0.z), __float2bfloat16_rn(v0.w));
        h[2] = __nv_bfloat162(__float2bfloat16_rn(v1.x), __float2bfloat16_rn(v1.y));
        h[3] = __nv_bfloat162(__float2bfloat16_rn(v1.z), __float2bfloat16_rn(v1.w));
        dst[lane * 2 + j] = *reinterpret_cast<uint4*>(h);
    }
#pragma unroll
    for (int off = 16; off; off >>= 1) s += __shfl_xor_sync(0xFFFFFFFFu, s, off);
    if (lane == 0) {
        g_xnorm[row] = sqrtf(s);
        g_ccnt[row] = 0;
        g_rowmax[row] = 0u;      // below fenc(any float)
    }
}

__global__ void conv_e_kernel(const float* __restrict__ e) {
    int row = (blockIdx.x * blockDim.x + threadIdx.x) >> 5;
    int lane = threadIdx.x & 31;
    if (row >= K_CODES) return;
    const float4* src = reinterpret_cast<const float4*>(e + (size_t)row * DDIM);
    uint4* dst = reinterpret_cast<uint4*>(g_eb + (size_t)row * DDIM);
    float s = 0.f;
#pragma unroll
    for (int j = 0; j < 2; j++) {
        __nv_bfloat162 h[4];
        float4 v0 = src[lane * 4 + j * 2];
        float4 v1 = src[lane * 4 + j * 2 + 1];
        s += v0.x*v0.x + v0.y*v0.y + v0.z*v0.z + v0.w*v0.w;
        s += v1.x*v1.x + v1.y*v1.y + v1.z*v1.z + v1.w*v1.w;
        h[0] = __nv_bfloat162(__float2bfloat16_rn(v0.x), __float2bfloat16_rn(v0.y));
        h[1] = __nv_bfloat162(__float2bfloat16_rn(v0.z), __float2bfloat16_rn(v0.w));
        h[2] = __nv_bfloat162(__float2bfloat16_rn(v1.x), __float2bfloat16_rn(v1.y));
        h[3] = __nv_bfloat162(__float2bfloat16_rn(v1.z), __float2bfloat16_rn(v1.w));
        dst[lane * 2 + j] = *reinterpret_cast<uint4*>(h);
    }
#pragma unroll
    for (int off = 16; off; off >>= 1) s += __shfl_xor_sync(0xFFFFFFFFu, s, off);
    if (lane == 0) {
        g_bias[row] = -0.5f * s;
        atomicMax(&g_emax2, __float_as_int(s));
    }
}

// ---------------------------------------------------------------------------
// GEMM (round-3 mainloop) + smem-staged, register-light candidate epilogue.
// ---------------------------------------------------------------------------
extern __shared__ char smem_g[];

__device__ __forceinline__ void gemm_issue(uint32_t smb, int stage, int row0, int col0,
                                           int chunk, int tid) {
    const int d0 = chunk * BKH;
    const uint32_t st = smb + stage * STAGE_B;
#pragma unroll
    for (int it = 0; it < 6; it++) {
        int i = tid + it * 256;
        int r = i >> 2, c = i & 3;
        if (r < BM) {
            cp16(st + r * ROWSTR_B + c * 16, g_xb + (size_t)(row0 + r) * DDIM + d0 + c * 8);
        } else {
            int r2 = r - BM;
            cp16(st + BM * ROWSTR_B + r2 * ROWSTR_B + c * 16,
                 g_eb + (size_t)(col0 + r2) * DDIM + d0 + c * 8);
        }
    }
}

__global__ __launch_bounds__(256, 1) void gemm_kernel() {
    const int tid = threadIdx.x;
    const int lane = tid & 31;
    const int wid = tid >> 5;
    const int wm = wid >> 2;
    const int wn = wid & 3;
    const int g = lane >> 2;
    const int q = lane & 3;
    const int col0 = blockIdx.x * BN;
    const int row0 = blockIdx.y * BM;
    const uint32_t smb = smem_u32(smem_g);

    float acc[4][8][4];
#pragma unroll
    for (int mt = 0; mt < 4; mt++)
#pragma unroll
        for (int nt = 0; nt < 8; nt++)
#pragma unroll
            for (int c = 0; c < 4; c++) acc[mt][nt][c] = 0.f;

    gemm_issue(smb, 0, row0, col0, 0, tid); CP_COMMIT();
    gemm_issue(smb, 1, row0, col0, 1, tid); CP_COMMIT();

    for (int ch = 0; ch < NCHUNK; ch++) {
        if (ch + 2 < NCHUNK) gemm_issue(smb, (ch + 2) % NSTAGE, row0, col0, ch + 2, tid);
        CP_COMMIT();
        CP_WAIT2();
        __syncthreads();

        const uint32_t* sa = reinterpret_cast<const uint32_t*>(smem_g + (ch % NSTAGE) * STAGE_B);
        const uint32_t* sb = sa + BM * (ROWSTR_B / 4);

#pragma unroll
        for (int s = 0; s < 2; s++) {
            const int s8 = s * 8;
            uint32_t a[4][4], b[8][2];
#pragma unroll
            for (int mt = 0; mt < 4; mt++) {
                int r = wm * 64 + mt * 16 + g;
                a[mt][0] = sa[r * 20 + q + s8];
                a[mt][1] = sa[(r + 8) * 20 + q + s8];
                a[mt][2] = sa[r * 20 + q + 4 + s8];
                a[mt][3] = sa[(r + 8) * 20 + q + 4 + s8];
            }
#pragma unroll
            for (int nt = 0; nt < 8; nt++) {
                int n = wn * 64 + nt * 8 + g;
                b[nt][0] = sb[n * 20 + q + s8];
                b[nt][1] = sb[n * 20 + q + 4 + s8];
            }
#pragma unroll
            for (int mt = 0; mt < 4; mt++)
#pragma unroll
                for (int nt = 0; nt < 8; nt++)
                    mma_bf16(acc[mt][nt], a[mt], b[nt]);
        }
        __syncthreads();
    }

    // ============ epilogue phase 1: dump scores to smem (bf16) ============
    __nv_bfloat162* sc = reinterpret_cast<__nv_bfloat162*>(smem_g);   // [128][128] bf162
    float* bias_sm = reinterpret_cast<float*>(smem_g + 65536);
    for (int i = tid; i < BN; i += 256) bias_sm[i] = g_bias[col0 + i];

#pragma unroll
    for (int mt = 0; mt < 4; mt++) {
        int r1 = wm * 64 + mt * 16 + g;
#pragma unroll
        for (int nt = 0; nt < 8; nt++) {
            int cl = (wn * 64 + nt * 8 + q * 2) >> 1;   // bf162 column
            sc[r1 * 128 + cl] = __nv_bfloat162(__float2bfloat16_rn(acc[mt][nt][0]),
                                               __float2bfloat16_rn(acc[mt][nt][1]));
            sc[(r1 + 8) * 128 + cl] = __nv_bfloat162(__float2bfloat16_rn(acc[mt][nt][2]),
                                                     __float2bfloat16_rn(acc[mt][nt][3]));
        }
    }
    __syncthreads();

    // ============ epilogue phase 2: register-light scan from smem ============
    {
        const int r = tid >> 1;          // 0..127
        const int h = tid & 1;           // col half
        const int grow = row0 + r;
        const __nv_bfloat162* rowp = sc + r * 128 + h * 64;
        const float* bp = bias_sm + h * 128;

        float m = -CUDART_INF_F;
#pragma unroll 8
        for (int j = 0; j < 64; j++) {
            __nv_bfloat162 v = rowp[j];
            float s0 = __bfloat162float(v.x) + bp[j * 2];
            float s1 = __bfloat162float(v.y) + bp[j * 2 + 1];
            m = fmaxf(m, fmaxf(s0, s1));
        }
        // combine halves (paired lanes differ in bit 0)
        m = fmaxf(m, __shfl_xor_sync(0xFFFFFFFFu, m, 1));

        uint32_t run = 0;
        if (h == 0) {
            uint32_t enc = fenc(m);
            uint32_t old = atomicMax(&g_rowmax[grow], enc);
            run = old > enc ? old : enc;
        }
        run = __shfl_sync(0xFFFFFFFFu, run, lane & ~1);

        const float emax = sqrtf(__int_as_float(g_emax2));
        const float thr = fdec(run) - (0.02f * g_xnorm[grow] * emax + 1.0f);

#pragma unroll 8
        for (int j = 0; j < 64; j++) {
            __nv_bfloat162 v = rowp[j];
            float s0 = __bfloat162float(v.x) + bp[j * 2];
            float s1 = __bfloat162float(v.y) + bp[j * 2 + 1];
            if (s0 >= thr) {
                int p = atomicAdd(&g_ccnt[grow], 1);
                if (p < MAXC) {
                    g_cidx[(size_t)grow * MAXC + p] = col0 + h * 128 + j * 2;
                    g_csc[(size_t)grow * MAXC + p] = s0;
                }
            }
            if (s1 >= thr) {
                int p = atomicAdd(&g_ccnt[grow], 1);
                if (p < MAXC) {
                    g_cidx[(size_t)grow * MAXC + p] = col0 + h * 128 + j * 2 + 1;
                    g_csc[(size_t)grow * MAXC + p] = s1;
                }
            }
        }
    }
}

// ---------------------------------------------------------------------------
// Select + gather fused: warp per row.
// ---------------------------------------------------------------------------
__global__ __launch_bounds__(256) void select_kernel(const float* __restrict__ x,
                                                     const float* __restrict__ embed,
                                                     float* __restrict__ out, int write_ind) {
    const int row = blockIdx.x * 8 + (threadIdx.x >> 5);
    const int lane = threadIdx.x & 31;
    if (row >= N_ROWS) return;

    const float4* x4 = reinterpret_cast<const float4*>(x + (size_t)row * DDIM);
    float4 xv[4];
#pragma unroll
    for (int j = 0; j < 4; j++) xv[j] = x4[lane + 32 * j];

    const int n = g_ccnt[row];
    float best = -CUDART_INF_F;
    int bi = K_CODES;

    if (n <= MAXC) {
        float cmax = -CUDART_INF_F;
        for (int i = lane; i < n; i += 32) cmax = fmaxf(cmax, g_csc[(size_t)row * MAXC + i]);
#pragma unroll
        for (int off = 16; off; off >>= 1) cmax = fmaxf(cmax, __shfl_xor_sync(0xFFFFFFFFu, cmax, off));
        const float thr = cmax - (0.02f * g_xnorm[row] * sqrtf(__int_as_float(g_emax2)) + 1.0f);

        for (int ci = 0; ci < n; ci++) {
            float asc = g_csc[(size_t)row * MAXC + ci];
            if (asc < thr) continue;
            int k = g_cidx[(size_t)row * MAXC + ci];
            const float4* e4 = reinterpret_cast<const float4*>(embed + (size_t)k * DDIM);
            float s = 0.f;
#pragma unroll
            for (int j = 0; j < 4; j++) {
                float4 ev = e4[lane + 32 * j];
                s += xv[j].x * ev.x + xv[j].y * ev.y + xv[j].z * ev.z + xv[j].w * ev.w;
            }
#pragma unroll
            for (int off = 16; off; off >>= 1) s += __shfl_xor_sync(0xFFFFFFFFu, s, off);
            float v = s + g_bias[k];
            if (v > best || (v == best && k < bi)) { best = v; bi = k; }
        }
    } else {
        // overflow fallback: exact full scan
        for (int k = lane; k < K_CODES; k += 32) {
            const float4* e4 = reinterpret_cast<const float4*>(embed + (size_t)k * DDIM);
            float s = 0.f;
            for (int j = 0; j < DDIM / 4; j++) {
                float4 ev = e4[j];
                float4 xw = x4[j];
                s += xw.x * ev.x + xw.y * ev.y + xw.z * ev.z + xw.w * ev.w;
            }
            float v = s + g_bias[k];
            if (v > best || (v == best && k < bi)) { best = v; bi = k; }
        }
#pragma unroll
        for (int off = 16; off; off >>= 1) {
            float ov = __shfl_xor_sync(0xFFFFFFFFu, best, off);
            int   oi = __shfl_xor_sync(0xFFFFFFFFu, bi, off);
            if (ov > best || (ov == best && oi < bi)) { best = ov; bi = oi; }
        }
    }

    bi = __shfl_sync(0xFFFFFFFFu, bi, 0);

    // fused gather
    const float4* src = reinterpret_cast<const float4*>(embed + (size_t)bi * DDIM);
    float4* dst = reinterpret_cast<float4*>(out + (size_t)row * DDIM);
#pragma unroll
    for (int j = 0; j < 4; j++) dst[lane + 32 * j] = src[lane + 32 * j];
    if (write_ind && lane == 0) out[(size_t)N_ROWS * DDIM + row] = (float)bi;
}

// ---------------------------------------------------------------------------
extern "C" void kernel_launch(void* const* d_in, const int* in_sizes, int n_in,
                              void* d_out, int out_size) {
    const float* x     = (const float*)d_in[0];
    const float* embed = (const float*)d_in[1];
    float* out = (float*)d_out;
    (void)in_sizes; (void)n_in;
    int write_ind = (out_size >= N_ROWS * DDIM + N_ROWS) ? 1 : 0;

    cudaFuncSetAttribute(gemm_kernel, cudaFuncAttributeMaxDynamicSharedMemorySize, SMEM_GEMM);

    conv_x_kernel<<<N_ROWS / 8, 256>>>(x);
    conv_e_kernel<<<K_CODES / 8, 256>>>(embed);
    gemm_kernel<<<dim3(K_CODES / BN, N_ROWS / BM), 256, SMEM_GEMM>>>();
    select_kernel<<<N_ROWS / 8, 256>>>(x, embed, out, write_ind);
}

// round 7
// speedup vs baseline: 58.5346x; 1.2422x over previous
#include <cuda_runtime.h>
#include <cuda_bf16.h>
#include <math_constants.h>
#include <cstdint>

#define DDIM    512
#define N_ROWS  16384
#define K_CODES 8192

// ---- GEMM tiling (round-3 proven shape) ----
#define BM      128
#define BN      256
#define BKH     32
#define NCHUNK  (DDIM / BKH)  // 16
#define ROWSTR_B 80           // 32 halves + pad (20 u32)
#define STAGE_B ((BM + BN) * ROWSTR_B)   // 30720
#define NSTAGE  3
#define SMEM_GEMM (NSTAGE * STAGE_B)     // 92160

#define MAXCAND 64

// ---- device scratch (allocation-free) ----
__device__ __nv_bfloat16 g_xb[(size_t)N_ROWS * DDIM];
__device__ __nv_bfloat16 g_eb[(size_t)K_CODES * DDIM];
__device__ __align__(16) float g_bias[K_CODES];        // -0.5*||e||^2
__device__ float g_xnorm[N_ROWS];
__device__ int   g_emax2;                               // max ||e||^2 (float bits); idempotent
__device__ __nv_bfloat162 g_sc2[(size_t)N_ROWS * (K_CODES / 2)];  // 256 MB approx scores

// ---------------------------------------------------------------------------
__device__ __forceinline__ uint32_t smem_u32(const void* p) {
    uint32_t a;
    asm("{ .reg .u64 t; cvta.to.shared.u64 t, %1; cvt.u32.u64 %0, t; }" : "=r"(a) : "l"(p));
    return a;
}
__device__ __forceinline__ void cp16(uint32_t dst, const void* src) {
    asm volatile("cp.async.cg.shared.global [%0], [%1], 16;" :: "r"(dst), "l"(src) : "memory");
}
#define CP_COMMIT() asm volatile("cp.async.commit_group;" ::: "memory")
#define CP_WAIT2()  asm volatile("cp.async.wait_group 2;" ::: "memory")

__device__ __forceinline__ void mma_bf16(float* d, const uint32_t* a, const uint32_t* b) {
    asm volatile(
        "mma.sync.aligned.m16n8k16.row.col.f32.bf16.bf16.f32 "
        "{%0,%1,%2,%3}, {%4,%5,%6,%7}, {%8,%9}, {%0,%1,%2,%3};"
        : "+f"(d[0]), "+f"(d[1]), "+f"(d[2]), "+f"(d[3])
        : "r"(a[0]), "r"(a[1]), "r"(a[2]), "r"(a[3]), "r"(b[0]), "r"(b[1]));
}

// ---------------------------------------------------------------------------
// conv_x: fp32 -> bf16, ||x||.  One warp per row.
// ---------------------------------------------------------------------------
__global__ void conv_x_kernel(const float* __restrict__ x) {
    int row = (blockIdx.x * blockDim.x + threadIdx.x) >> 5;
    int lane = threadIdx.x & 31;
    if (row >= N_ROWS) return;
    const float4* src = reinterpret_cast<const float4*>(x + (size_t)row * DDIM);
    uint4* dst = reinterpret_cast<uint4*>(g_xb + (size_t)row * DDIM);
    float s = 0.f;
#pragma unroll
    for (int j = 0; j < 2; j++) {
        __nv_bfloat162 h[4];
        float4 v0 = src[lane * 4 + j * 2];
        float4 v1 = src[lane * 4 + j * 2 + 1];
        s += v0.x*v0.x + v0.y*v0.y + v0.z*v0.z + v0.w*v0.w;
        s += v1.x*v1.x + v1.y*v1.y + v1.z*v1.z + v1.w*v1.w;
        h[0] = __nv_bfloat162(__float2bfloat16_rn(v0.x), __float2bfloat16_rn(v0.y));
        h[1] = __nv_bfloat162(__float2bfloat16_rn(v0.z), __float2bfloat16_rn(v0.w));
        h[2] = __nv_bfloat162(__float2bfloat16_rn(v1.x), __float2bfloat16_rn(v1.y));
        h[3] = __nv_bfloat162(__float2bfloat16_rn(v1.z), __float2bfloat16_rn(v1.w));
        dst[lane * 2 + j] = *reinterpret_cast<uint4*>(h);
    }
#pragma unroll
    for (int off = 16; off; off >>= 1) s += __shfl_xor_sync(0xFFFFFFFFu, s, off);
    if (lane == 0) g_xnorm[row] = sqrtf(s);
}

__global__ void conv_e_kernel(const float* __restrict__ e) {
    int row = (blockIdx.x * blockDim.x + threadIdx.x) >> 5;
    int lane = threadIdx.x & 31;
    if (row >= K_CODES) return;
    const float4* src = reinterpret_cast<const float4*>(e + (size_t)row * DDIM);
    uint4* dst = reinterpret_cast<uint4*>(g_eb + (size_t)row * DDIM);
    float s = 0.f;
#pragma unroll
    for (int j = 0; j < 2; j++) {
        __nv_bfloat162 h[4];
        float4 v0 = src[lane * 4 + j * 2];
        float4 v1 = src[lane * 4 + j * 2 + 1];
        s += v0.x*v0.x + v0.y*v0.y + v0.z*v0.z + v0.w*v0.w;
        s += v1.x*v1.x + v1.y*v1.y + v1.z*v1.z + v1.w*v1.w;
        h[0] = __nv_bfloat162(__float2bfloat16_rn(v0.x), __float2bfloat16_rn(v0.y));
        h[1] = __nv_bfloat162(__float2bfloat16_rn(v0.z), __float2bfloat16_rn(v0.w));
        h[2] = __nv_bfloat162(__float2bfloat16_rn(v1.x), __float2bfloat16_rn(v1.y));
        h[3] = __nv_bfloat162(__float2bfloat16_rn(v1.z), __float2bfloat16_rn(v1.w));
        dst[lane * 2 + j] = *reinterpret_cast<uint4*>(h);
    }
#pragma unroll
    for (int off = 16; off; off >>= 1) s += __shfl_xor_sync(0xFFFFFFFFu, s, off);
    if (lane == 0) {
        g_bias[row] = -0.5f * s;
        atomicMax(&g_emax2, __float_as_int(s));
    }
}

// ---------------------------------------------------------------------------
// GEMM: round-3 mainloop verbatim; epilogue = plain bf16 score stores.
// ---------------------------------------------------------------------------
extern __shared__ char smem_g[];

__device__ __forceinline__ void gemm_issue(uint32_t smb, int stage, int row0, int col0,
                                           int chunk, int tid) {
    const int d0 = chunk * BKH;
    const uint32_t st = smb + stage * STAGE_B;
#pragma unroll
    for (int it = 0; it < 6; it++) {
        int i = tid + it * 256;
        int r = i >> 2, c = i & 3;
        if (r < BM) {
            cp16(st + r * ROWSTR_B + c * 16, g_xb + (size_t)(row0 + r) * DDIM + d0 + c * 8);
        } else {
            int r2 = r - BM;
            cp16(st + BM * ROWSTR_B + r2 * ROWSTR_B + c * 16,
                 g_eb + (size_t)(col0 + r2) * DDIM + d0 + c * 8);
        }
    }
}

__global__ __launch_bounds__(256, 1) void gemm_kernel() {
    const int tid = threadIdx.x;
    const int lane = tid & 31;
    const int wid = tid >> 5;
    const int wm = wid >> 2;
    const int wn = wid & 3;
    const int g = lane >> 2;
    const int q = lane & 3;
    const int col0 = blockIdx.x * BN;
    const int row0 = blockIdx.y * BM;
    const uint32_t smb = smem_u32(smem_g);

    float acc[4][8][4];
#pragma unroll
    for (int mt = 0; mt < 4; mt++)
#pragma unroll
        for (int nt = 0; nt < 8; nt++)
#pragma unroll
            for (int c = 0; c < 4; c++) acc[mt][nt][c] = 0.f;

    gemm_issue(smb, 0, row0, col0, 0, tid); CP_COMMIT();
    gemm_issue(smb, 1, row0, col0, 1, tid); CP_COMMIT();

    for (int ch = 0; ch < NCHUNK; ch++) {
        if (ch + 2 < NCHUNK) gemm_issue(smb, (ch + 2) % NSTAGE, row0, col0, ch + 2, tid);
        CP_COMMIT();
        CP_WAIT2();
        __syncthreads();

        const uint32_t* sa = reinterpret_cast<const uint32_t*>(smem_g + (ch % NSTAGE) * STAGE_B);
        const uint32_t* sb = sa + BM * (ROWSTR_B / 4);

#pragma unroll
        for (int s = 0; s < 2; s++) {
            const int s8 = s * 8;
            uint32_t a[4][4], b[8][2];
#pragma unroll
            for (int mt = 0; mt < 4; mt++) {
                int r = wm * 64 + mt * 16 + g;
                a[mt][0] = sa[r * 20 + q + s8];
                a[mt][1] = sa[(r + 8) * 20 + q + s8];
                a[mt][2] = sa[r * 20 + q + 4 + s8];
                a[mt][3] = sa[(r + 8) * 20 + q + 4 + s8];
            }
#pragma unroll
            for (int nt = 0; nt < 8; nt++) {
                int n = wn * 64 + nt * 8 + g;
                b[nt][0] = sb[n * 20 + q + s8];
                b[nt][1] = sb[n * 20 + q + 4 + s8];
            }
#pragma unroll
            for (int mt = 0; mt < 4; mt++)
#pragma unroll
                for (int nt = 0; nt < 8; nt++)
                    mma_bf16(acc[mt][nt], a[mt], b[nt]);
        }
        __syncthreads();
    }

    // epilogue: plain bf16 score stores (no bias, no reductions)
#pragma unroll
    for (int mt = 0; mt < 4; mt++) {
        int r = row0 + wm * 64 + mt * 16 + g;
#pragma unroll
        for (int nt = 0; nt < 8; nt++) {
            int c2 = (col0 >> 1) + wn * 32 + nt * 4 + q;    // bf162 column
            g_sc2[(size_t)r * (K_CODES / 2) + c2] =
                __nv_bfloat162(__float2bfloat16_rn(acc[mt][nt][0]),
                               __float2bfloat16_rn(acc[mt][nt][1]));
            g_sc2[(size_t)(r + 8) * (K_CODES / 2) + c2] =
                __nv_bfloat162(__float2bfloat16_rn(acc[mt][nt][2]),
                               __float2bfloat16_rn(acc[mt][nt][3]));
        }
    }
}

// ---------------------------------------------------------------------------
// Select + gather: block per row. max scan -> margin candidates -> exact
// fp32 rescore -> write output row + index.
// ---------------------------------------------------------------------------
__global__ __launch_bounds__(256) void select_kernel(const float* __restrict__ x,
                                                     const float* __restrict__ embed,
                                                     float* __restrict__ out, int write_ind) {
    __shared__ __align__(16) float xs[DDIM];
    __shared__ float red[8];
    __shared__ float bcast;
    __shared__ int   cands[MAXCAND];
    __shared__ float cvals[MAXCAND];
    __shared__ int   cnt;
    __shared__ float rv[256];
    __shared__ int   ri[256];
    __shared__ int   bsel;

    const int row = blockIdx.x;
    const int tid = threadIdx.x;
    const int lane = tid & 31;
    const int wid = tid >> 5;

    for (int i = tid; i < DDIM; i += 256) xs[i] = x[(size_t)row * DDIM + i];
    if (tid == 0) cnt = 0;

    const uint4* s16 = reinterpret_cast<const uint4*>(g_sc2 + (size_t)row * (K_CODES / 2));
    const float4* b4 = reinterpret_cast<const float4*>(g_bias);

    // pass 1: row max of approx scores + bias (each uint4 = 8 scores)
    float m = -CUDART_INF_F;
    for (int i = tid; i < K_CODES / 8; i += 256) {
        uint4 u = s16[i];
        float4 b0 = b4[i * 2], b1 = b4[i * 2 + 1];
        float2 p0 = __bfloat1622float2(*reinterpret_cast<__nv_bfloat162*>(&u.x));
        float2 p1 = __bfloat1622float2(*reinterpret_cast<__nv_bfloat162*>(&u.y));
        float2 p2 = __bfloat1622float2(*reinterpret_cast<__nv_bfloat162*>(&u.z));
        float2 p3 = __bfloat1622float2(*reinterpret_cast<__nv_bfloat162*>(&u.w));
        m = fmaxf(m, fmaxf(fmaxf(p0.x + b0.x, p0.y + b0.y), fmaxf(p1.x + b0.z, p1.y + b0.w)));
        m = fmaxf(m, fmaxf(fmaxf(p2.x + b1.x, p2.y + b1.y), fmaxf(p3.x + b1.z, p3.y + b1.w)));
    }
#pragma unroll
    for (int off = 16; off; off >>= 1) m = fmaxf(m, __shfl_xor_sync(0xFFFFFFFFu, m, off));
    if (lane == 0) red[wid] = m;
    __syncthreads();
    if (tid == 0) {
        float mm = red[0];
#pragma unroll
        for (int i = 1; i < 8; i++) mm = fmaxf(mm, red[i]);
        bcast = mm;
    }
    __syncthreads();

    const float margin = 0.02f * g_xnorm[row] * sqrtf(__int_as_float(g_emax2)) + 1.0f;
    const float thr = bcast - margin;

    // pass 2: candidates (L1-hot reread)
    for (int i = tid; i < K_CODES / 8; i += 256) {
        uint4 u = s16[i];
        float4 b0 = b4[i * 2], b1 = b4[i * 2 + 1];
        float2 p0 = __bfloat1622float2(*reinterpret_cast<__nv_bfloat162*>(&u.x));
        float2 p1 = __bfloat1622float2(*reinterpret_cast<__nv_bfloat162*>(&u.y));
        float2 p2 = __bfloat1622float2(*reinterpret_cast<__nv_bfloat162*>(&u.z));
        float2 p3 = __bfloat1622float2(*reinterpret_cast<__nv_bfloat162*>(&u.w));
        float val[8] = {p0.x + b0.x, p0.y + b0.y, p1.x + b0.z, p1.y + b0.w,
                        p2.x + b1.x, p2.y + b1.y, p3.x + b1.z, p3.y + b1.w};
#pragma unroll
        for (int c = 0; c < 8; c++) {
            if (val[c] >= thr) {
                int p = atomicAdd(&cnt, 1);
                if (p < MAXCAND) cands[p] = i * 8 + c;
            }
        }
    }
    __syncthreads();
    const int n = cnt;

    int bi = K_CODES;
    if (n <= MAXCAND) {
        const float4* xs4 = reinterpret_cast<const float4*>(xs);
        for (int ci = wid; ci < n; ci += 8) {
            int k = cands[ci];
            const float4* e4 = reinterpret_cast<const float4*>(embed + (size_t)k * DDIM);
            float s = 0.f;
#pragma unroll
            for (int j = 0; j < 4; j++) {
                float4 ev = e4[lane + 32 * j];
                float4 xv = xs4[lane + 32 * j];
                s += xv.x * ev.x + xv.y * ev.y + xv.z * ev.z + xv.w * ev.w;
            }
#pragma unroll
            for (int off = 16; off; off >>= 1) s += __shfl_xor_sync(0xFFFFFFFFu, s, off);
            if (lane == 0) cvals[ci] = s + g_bias[k];
        }
        __syncthreads();
        if (tid == 0) {
            float best = -CUDART_INF_F;
            for (int ci = 0; ci < n; ci++) {
                float v = cvals[ci];
                int k = cands[ci];
                if (v > best || (v == best && k < bi)) { best = v; bi = k; }
            }
            bsel = bi;
        }
    } else {
        // overflow fallback: full exact scan
        const float4* xs4 = reinterpret_cast<const float4*>(xs);
        float best = -CUDART_INF_F;
        for (int k = tid; k < K_CODES; k += 256) {
            const float4* e4 = reinterpret_cast<const float4*>(embed + (size_t)k * DDIM);
            float s = 0.f;
            for (int j = 0; j < DDIM / 4; j++) {
                float4 ev = e4[j];
                float4 xv = xs4[j];
                s += xv.x * ev.x + xv.y * ev.y + xv.z * ev.z + xv.w * ev.w;
            }
            float v = s + g_bias[k];
            if (v > best || (v == best && k < bi)) { best = v; bi = k; }
        }
        rv[tid] = best; ri[tid] = bi;
        __syncthreads();
        if (tid == 0) {
            for (int t = 1; t < 256; t++) {
                if (rv[t] > best || (rv[t] == best && ri[t] < bi)) { best = rv[t]; bi = ri[t]; }
            }
            bsel = bi;
        }
    }
    __syncthreads();
    bi = bsel;

    // fused gather
    const float4* src = reinterpret_cast<const float4*>(embed + (size_t)bi * DDIM);
    float4* dst = reinterpret_cast<float4*>(out + (size_t)row * DDIM);
    for (int i = tid; i < DDIM / 4; i += 256) dst[i] = src[i];
    if (write_ind && tid == 0) out[(size_t)N_ROWS * DDIM + row] = (float)bi;
}

// ---------------------------------------------------------------------------
extern "C" void kernel_launch(void* const* d_in, const int* in_sizes, int n_in,
                              void* d_out, int out_size) {
    const float* x     = (const float*)d_in[0];
    const float* embed = (const float*)d_in[1];
    float* out = (float*)d_out;
    (void)in_sizes; (void)n_in;
    int write_ind = (out_size >= N_ROWS * DDIM + N_ROWS) ? 1 : 0;

    cudaFuncSetAttribute(gemm_kernel, cudaFuncAttributeMaxDynamicSharedMemorySize, SMEM_GEMM);

    conv_x_kernel<<<N_ROWS / 8, 256>>>(x);
    conv_e_kernel<<<K_CODES / 8, 256>>>(embed);
    gemm_kernel<<<dim3(K_CODES / BN, N_ROWS / BM), 256, SMEM_GEMM>>>();
    select_kernel<<<N_ROWS, 256>>>(x, embed, out, write_ind);
}

// round 8
// speedup vs baseline: 60.0033x; 1.0251x over previous
#include <cuda_runtime.h>
#include <cuda_bf16.h>
#include <math_constants.h>
#include <cstdint>

#define DDIM    512
#define N_ROWS  16384
#define K_CODES 8192

// ---- GEMM tiling ----
#define BM      128
#define BN      256
#define BKH     32
#define NCHUNK  (DDIM / BKH)  // 16
#define ROWSTR_B 80           // 32 halves + pad -> ldmatrix bank-permutation friendly
#define STAGE_B ((BM + BN) * ROWSTR_B)   // 30720
#define NSTAGE  3
#define SMEM_GEMM (NSTAGE * STAGE_B)     // 92160

#define MAXCAND 64

// ---- device scratch (allocation-free) ----
__device__ __nv_bfloat16 g_xb[(size_t)N_ROWS * DDIM];
__device__ __nv_bfloat16 g_eb[(size_t)K_CODES * DDIM];
__device__ __align__(16) float g_bias[K_CODES];        // -0.5*||e||^2
__device__ float g_xnorm[N_ROWS];
__device__ int   g_emax2;                               // max ||e||^2 (float bits); idempotent
__device__ __nv_bfloat162 g_sc2[(size_t)N_ROWS * (K_CODES / 2)];  // scores WITH bias folded

// ---------------------------------------------------------------------------
__device__ __forceinline__ uint32_t smem_u32(const void* p) {
    uint32_t a;
    asm("{ .reg .u64 t; cvta.to.shared.u64 t, %1; cvt.u32.u64 %0, t; }" : "=r"(a) : "l"(p));
    return a;
}
__device__ __forceinline__ void cp16(uint32_t dst, const void* src) {
    asm volatile("cp.async.cg.shared.global [%0], [%1], 16;" :: "r"(dst), "l"(src) : "memory");
}
#define CP_COMMIT() asm volatile("cp.async.commit_group;" ::: "memory")
#define CP_WAIT2()  asm volatile("cp.async.wait_group 2;" ::: "memory")

__device__ __forceinline__ void ldsm4(uint32_t* r, uint32_t addr) {
    asm volatile("ldmatrix.sync.aligned.m8n8.x4.shared.b16 {%0,%1,%2,%3}, [%4];"
                 : "=r"(r[0]), "=r"(r[1]), "=r"(r[2]), "=r"(r[3]) : "r"(addr));
}
__device__ __forceinline__ void mma_bf16(float* d, const uint32_t* a, const uint32_t* b) {
    asm volatile(
        "mma.sync.aligned.m16n8k16.row.col.f32.bf16.bf16.f32 "
        "{%0,%1,%2,%3}, {%4,%5,%6,%7}, {%8,%9}, {%0,%1,%2,%3};"
        : "+f"(d[0]), "+f"(d[1]), "+f"(d[2]), "+f"(d[3])
        : "r"(a[0]), "r"(a[1]), "r"(a[2]), "r"(a[3]), "r"(b[0]), "r"(b[1]));
}

// ---------------------------------------------------------------------------
// conv_x: fp32 -> bf16, ||x||.  One warp per row.
// ---------------------------------------------------------------------------
__global__ void conv_x_kernel(const float* __restrict__ x) {
    int row = (blockIdx.x * blockDim.x + threadIdx.x) >> 5;
    int lane = threadIdx.x & 31;
    if (row >= N_ROWS) return;
    const float4* src = reinterpret_cast<const float4*>(x + (size_t)row * DDIM);
    uint4* dst = reinterpret_cast<uint4*>(g_xb + (size_t)row * DDIM);
    float s = 0.f;
#pragma unroll
    for (int j = 0; j < 2; j++) {
        __nv_bfloat162 h[4];
        float4 v0 = src[lane * 4 + j * 2];
        float4 v1 = src[lane * 4 + j * 2 + 1];
        s += v0.x*v0.x + v0.y*v0.y + v0.z*v0.z + v0.w*v0.w;
        s += v1.x*v1.x + v1.y*v1.y + v1.z*v1.z + v1.w*v1.w;
        h[0] = __nv_bfloat162(__float2bfloat16_rn(v0.x), __float2bfloat16_rn(v0.y));
        h[1] = __nv_bfloat162(__float2bfloat16_rn(v0.z), __float2bfloat16_rn(v0.w));
        h[2] = __nv_bfloat162(__float2bfloat16_rn(v1.x), __float2bfloat16_rn(v1.y));
        h[3] = __nv_bfloat162(__float2bfloat16_rn(v1.z), __float2bfloat16_rn(v1.w));
        dst[lane * 2 + j] = *reinterpret_cast<uint4*>(h);
    }
#pragma unroll
    for (int off = 16; off; off >>= 1) s += __shfl_xor_sync(0xFFFFFFFFu, s, off);
    if (lane == 0) g_xnorm[row] = sqrtf(s);
}

__global__ void conv_e_kernel(const float* __restrict__ e) {
    int row = (blockIdx.x * blockDim.x + threadIdx.x) >> 5;
    int lane = threadIdx.x & 31;
    if (row >= K_CODES) return;
    const float4* src = reinterpret_cast<const float4*>(e + (size_t)row * DDIM);
    uint4* dst = reinterpret_cast<uint4*>(g_eb + (size_t)row * DDIM);
    float s = 0.f;
#pragma unroll
    for (int j = 0; j < 2; j++) {
        __nv_bfloat162 h[4];
        float4 v0 = src[lane * 4 + j * 2];
        float4 v1 = src[lane * 4 + j * 2 + 1];
        s += v0.x*v0.x + v0.y*v0.y + v0.z*v0.z + v0.w*v0.w;
        s += v1.x*v1.x + v1.y*v1.y + v1.z*v1.z + v1.w*v1.w;
        h[0] = __nv_bfloat162(__float2bfloat16_rn(v0.x), __float2bfloat16_rn(v0.y));
        h[1] = __nv_bfloat162(__float2bfloat16_rn(v0.z), __float2bfloat16_rn(v0.w));
        h[2] = __nv_bfloat162(__float2bfloat16_rn(v1.x), __float2bfloat16_rn(v1.y));
        h[3] = __nv_bfloat162(__float2bfloat16_rn(v1.z), __float2bfloat16_rn(v1.w));
        dst[lane * 2 + j] = *reinterpret_cast<uint4*>(h);
    }
#pragma unroll
    for (int off = 16; off; off >>= 1) s += __shfl_xor_sync(0xFFFFFFFFu, s, off);
    if (lane == 0) {
        g_bias[row] = -0.5f * s;
        atomicMax(&g_emax2, __float_as_int(s));
    }
}

// ---------------------------------------------------------------------------
// GEMM: ldmatrix mainloop; epilogue stores bf16(score + bias).
// ---------------------------------------------------------------------------
extern __shared__ char smem_g[];

__device__ __forceinline__ void gemm_issue(uint32_t smb, int stage, int row0, int col0,
                                           int chunk, int tid) {
    const int d0 = chunk * BKH;
    const uint32_t st = smb + stage * STAGE_B;
#pragma unroll
    for (int it = 0; it < 6; it++) {
        int i = tid + it * 256;
        int r = i >> 2, c = i & 3;
        if (r < BM) {
            cp16(st + r * ROWSTR_B + c * 16, g_xb + (size_t)(row0 + r) * DDIM + d0 + c * 8);
        } else {
            int r2 = r - BM;
            cp16(st + BM * ROWSTR_B + r2 * ROWSTR_B + c * 16,
                 g_eb + (size_t)(col0 + r2) * DDIM + d0 + c * 8);
        }
    }
}

__global__ __launch_bounds__(256, 1) void gemm_kernel() {
    const int tid = threadIdx.x;
    const int lane = tid & 31;
    const int wid = tid >> 5;
    const int wm = wid >> 2;
    const int wn = wid & 3;
    const int g = lane >> 2;
    const int q = lane & 3;
    const int col0 = blockIdx.x * BN;
    const int row0 = blockIdx.y * BM;
    const uint32_t smb = smem_u32(smem_g);

    // ldmatrix per-lane address components
    const int a_row = wm * 64 + (lane & 15);            // + mt*16
    const int a_col = (lane >> 4) << 4;                 // 0 or 16 bytes; + s*32
    const int b_row = wn * 64 + (lane & 7) + ((lane & 16) ? 8 : 0);  // + ntp*16
    const int b_col = (lane & 8) ? 16 : 0;              // + s*32

    float acc[4][8][4];
#pragma unroll
    for (int mt = 0; mt < 4; mt++)
#pragma unroll
        for (int nt = 0; nt < 8; nt++)
#pragma unroll
            for (int c = 0; c < 4; c++) acc[mt][nt][c] = 0.f;

    gemm_issue(smb, 0, row0, col0, 0, tid); CP_COMMIT();
    gemm_issue(smb, 1, row0, col0, 1, tid); CP_COMMIT();

    for (int ch = 0; ch < NCHUNK; ch++) {
        if (ch + 2 < NCHUNK) gemm_issue(smb, (ch + 2) % NSTAGE, row0, col0, ch + 2, tid);
        CP_COMMIT();
        CP_WAIT2();
        __syncthreads();

        const uint32_t sa_b = smb + (ch % NSTAGE) * STAGE_B;
        const uint32_t sb_b = sa_b + BM * ROWSTR_B;
        const uint32_t a_base = sa_b + a_row * ROWSTR_B + a_col;
        const uint32_t b_base = sb_b + b_row * ROWSTR_B + b_col;

#pragma unroll
        for (int s = 0; s < 2; s++) {
            const int sc32 = s * 32;
            uint32_t a[4][4], b[4][4];
#pragma unroll
            for (int mt = 0; mt < 4; mt++)
                ldsm4(a[mt], a_base + mt * (16 * ROWSTR_B) + sc32);
#pragma unroll
            for (int ntp = 0; ntp < 4; ntp++)
                ldsm4(b[ntp], b_base + ntp * (16 * ROWSTR_B) + sc32);
#pragma unroll
            for (int mt = 0; mt < 4; mt++)
#pragma unroll
                for (int ntp = 0; ntp < 4; ntp++) {
                    mma_bf16(acc[mt][2 * ntp],     a[mt], &b[ntp][0]);
                    mma_bf16(acc[mt][2 * ntp + 1], a[mt], &b[ntp][2]);
                }
        }
        __syncthreads();
    }

    // epilogue: fold bias, store bf16 scores
    float bc0[8], bc1[8];
#pragma unroll
    for (int nt = 0; nt < 8; nt++) {
        int c = col0 + wn * 64 + nt * 8 + q * 2;
        bc0[nt] = __ldg(&g_bias[c]);
        bc1[nt] = __ldg(&g_bias[c + 1]);
    }
#pragma unroll
    for (int mt = 0; mt < 4; mt++) {
        int r = row0 + wm * 64 + mt * 16 + g;
#pragma unroll
        for (int nt = 0; nt < 8; nt++) {
            int c2 = (col0 >> 1) + wn * 32 + nt * 4 + q;
            g_sc2[(size_t)r * (K_CODES / 2) + c2] =
                __nv_bfloat162(__float2bfloat16_rn(acc[mt][nt][0] + bc0[nt]),
                               __float2bfloat16_rn(acc[mt][nt][1] + bc1[nt]));
            g_sc2[(size_t)(r + 8) * (K_CODES / 2) + c2] =
                __nv_bfloat162(__float2bfloat16_rn(acc[mt][nt][2] + bc0[nt]),
                               __float2bfloat16_rn(acc[mt][nt][3] + bc1[nt]));
        }
    }
}

// ---------------------------------------------------------------------------
// Select + gather: warp per row. bf16-SIMD max scan -> hge2 candidate filter
// -> exact fp32 rescore -> write output row + index.
// ---------------------------------------------------------------------------
__global__ __launch_bounds__(256) void select_kernel(const float* __restrict__ x,
                                                     const float* __restrict__ embed,
                                                     float* __restrict__ out, int write_ind) {
    __shared__ int cnt[8];
    __shared__ int cands[8][MAXCAND];

    const int wrow = threadIdx.x >> 5;
    const int row = blockIdx.x * 8 + wrow;
    const int lane = threadIdx.x & 31;
    if (row >= N_ROWS) return;

    if (lane == 0) cnt[wrow] = 0;
    __syncwarp();

    const float4* x4 = reinterpret_cast<const float4*>(x + (size_t)row * DDIM);
    float4 xv[4];
#pragma unroll
    for (int j = 0; j < 4; j++) xv[j] = x4[lane + 32 * j];

    const uint4* s16 = reinterpret_cast<const uint4*>(g_sc2 + (size_t)row * (K_CODES / 2));

    // pass 1: bf16 SIMD row max (scores already include bias)
    __nv_bfloat162 mm2 = __float2bfloat162_rn(-CUDART_INF_F);
#pragma unroll 4
    for (int j = 0; j < 32; j++) {
        uint4 u = s16[lane + 32 * j];
        __nv_bfloat162 p0 = *reinterpret_cast<__nv_bfloat162*>(&u.x);
        __nv_bfloat162 p1 = *reinterpret_cast<__nv_bfloat162*>(&u.y);
        __nv_bfloat162 p2 = *reinterpret_cast<__nv_bfloat162*>(&u.z);
        __nv_bfloat162 p3 = *reinterpret_cast<__nv_bfloat162*>(&u.w);
        mm2 = __hmax2(mm2, __hmax2(__hmax2(p0, p1), __hmax2(p2, p3)));
    }
    float m = fmaxf(__bfloat162float(mm2.x), __bfloat162float(mm2.y));
#pragma unroll
    for (int off = 16; off; off >>= 1) m = fmaxf(m, __shfl_xor_sync(0xFFFFFFFFu, m, off));

    const float margin = 0.02f * g_xnorm[row] * sqrtf(__int_as_float(g_emax2)) + 1.0f;
    const float thr = m - margin;
    const __nv_bfloat16 thr_b = __float2bfloat16_rd(thr);
    const __nv_bfloat162 thr2 = __nv_bfloat162(thr_b, thr_b);

    // pass 2: candidate filter (L1-hot reread)
    for (int j = 0; j < 32; j++) {
        const int i = lane + 32 * j;
        uint4 u = s16[i];
#pragma unroll
        for (int w = 0; w < 4; w++) {
            uint32_t uw = (&u.x)[w];
            __nv_bfloat162 v = *reinterpret_cast<__nv_bfloat162*>(&uw);
            __nv_bfloat162 ge = __hge2(v, thr2);
            if (*reinterpret_cast<uint32_t*>(&ge) != 0u) {
                float2 p = __bfloat1622float2(v);
                if (p.x >= thr) {
                    int pos = atomicAdd(&cnt[wrow], 1);
                    if (pos < MAXCAND) cands[wrow][pos] = i * 8 + w * 2;
                }
                if (p.y >= thr) {
                    int pos = atomicAdd(&cnt[wrow], 1);
                    if (pos < MAXCAND) cands[wrow][pos] = i * 8 + w * 2 + 1;
                }
            }
        }
    }
    __syncwarp();
    const int n = cnt[wrow];

    float best = -CUDART_INF_F;
    int bi = K_CODES;

    if (n <= MAXCAND) {
        for (int ci = 0; ci < n; ci++) {
            int k = cands[wrow][ci];
            const float4* e4 = reinterpret_cast<const float4*>(embed + (size_t)k * DDIM);
            float s = 0.f;
#pragma unroll
            for (int j = 0; j < 4; j++) {
                float4 ev = e4[lane + 32 * j];
                s += xv[j].x * ev.x + xv[j].y * ev.y + xv[j].z * ev.z + xv[j].w * ev.w;
            }
#pragma unroll
            for (int off = 16; off; off >>= 1) s += __shfl_xor_sync(0xFFFFFFFFu, s, off);
            float v = s + g_bias[k];
            if (v > best || (v == best && k < bi)) { best = v; bi = k; }
        }
    } else {
        // overflow fallback: exact full scan, lane-parallel
        for (int k = lane; k < K_CODES; k += 32) {
            const float4* e4 = reinterpret_cast<const float4*>(embed + (size_t)k * DDIM);
            float s = 0.f;
            for (int j = 0; j < DDIM / 4; j++) {
                float4 ev = e4[j];
                float4 xw = x4[j];
                s += xw.x * ev.x + xw.y * ev.y + xw.z * ev.z + xw.w * ev.w;
            }
            float v = s + g_bias[k];
            if (v > best || (v == best && k < bi)) { best = v; bi = k; }
        }
#pragma unroll
        for (int off = 16; off; off >>= 1) {
            float ov = __shfl_xor_sync(0xFFFFFFFFu, best, off);
            int   oi = __shfl_xor_sync(0xFFFFFFFFu, bi, off);
            if (ov > best || (ov == best && oi < bi)) { best = ov; bi = oi; }
        }
    }

    bi = __shfl_sync(0xFFFFFFFFu, bi, 0);

    // fused gather
    const float4* src = reinterpret_cast<const float4*>(embed + (size_t)bi * DDIM);
    float4* dst = reinterpret_cast<float4*>(out + (size_t)row * DDIM);
#pragma unroll
    for (int j = 0; j < 4; j++) dst[lane + 32 * j] = src[lane + 32 * j];
    if (write_ind && lane == 0) out[(size_t)N_ROWS * DDIM + row] = (float)bi;
}

// ---------------------------------------------------------------------------
extern "C" void kernel_launch(void* const* d_in, const int* in_sizes, int n_in,
                              void* d_out, int out_size) {
    const float* x     = (const float*)d_in[0];
    const float* embed = (const float*)d_in[1];
    float* out = (float*)d_out;
    (void)in_sizes; (void)n_in;
    int write_ind = (out_size >= N_ROWS * DDIM + N_ROWS) ? 1 : 0;

    cudaFuncSetAttribute(gemm_kernel, cudaFuncAttributeMaxDynamicSharedMemorySize, SMEM_GEMM);

    conv_x_kernel<<<N_ROWS / 8, 256>>>(x);
    conv_e_kernel<<<K_CODES / 8, 256>>>(embed);
    gemm_kernel<<<dim3(K_CODES / BN, N_ROWS / BM), 256, SMEM_GEMM>>>();
    select_kernel<<<N_ROWS / 8, 256>>>(x, embed, out, write_ind);
}

// round 9
// speedup vs baseline: 60.1768x; 1.0029x over previous
#include <cuda_runtime.h>
#include <cuda_bf16.h>
#include <math_constants.h>
#include <cstdint>

#define DDIM    512
#define N_ROWS  16384
#define K_CODES 8192

// ---- GEMM tiling ----
#define BM      128
#define BN      256
#define BKH     32
#define NCHUNK  (DDIM / BKH)  // 16
#define ROWSTR_B 80           // 32 halves + pad -> ldmatrix bank-permutation friendly
#define STAGE_B ((BM + BN) * ROWSTR_B)   // 30720
#define NSTAGE  3
#define SMEM_GEMM (NSTAGE * STAGE_B)     // 92160

#define MAXCAND 64

// ---- device scratch (allocation-free) ----
__device__ __nv_bfloat16 g_xb[(size_t)N_ROWS * DDIM];
__device__ __nv_bfloat16 g_eb[(size_t)K_CODES * DDIM];
__device__ __align__(16) float g_bias[K_CODES];        // -0.5*||e||^2
__device__ float g_xnorm[N_ROWS];
__device__ int   g_emax2;                               // max ||e||^2 (float bits); idempotent
__device__ __nv_bfloat162 g_sc2[(size_t)N_ROWS * (K_CODES / 2)];  // scores WITH bias folded

// ---------------------------------------------------------------------------
__device__ __forceinline__ uint32_t smem_u32(const void* p) {
    uint32_t a;
    asm("{ .reg .u64 t; cvta.to.shared.u64 t, %1; cvt.u32.u64 %0, t; }" : "=r"(a) : "l"(p));
    return a;
}
__device__ __forceinline__ void cp16(uint32_t dst, const void* src) {
    asm volatile("cp.async.cg.shared.global [%0], [%1], 16;" :: "r"(dst), "l"(src) : "memory");
}
#define CP_COMMIT() asm volatile("cp.async.commit_group;" ::: "memory")
#define CP_WAIT2()  asm volatile("cp.async.wait_group 2;" ::: "memory")

__device__ __forceinline__ void ldsm4(uint32_t* r, uint32_t addr) {
    asm volatile("ldmatrix.sync.aligned.m8n8.x4.shared.b16 {%0,%1,%2,%3}, [%4];"
                 : "=r"(r[0]), "=r"(r[1]), "=r"(r[2]), "=r"(r[3]) : "r"(addr));
}
__device__ __forceinline__ void mma_bf16(float* d, const uint32_t* a, const uint32_t* b) {
    asm volatile(
        "mma.sync.aligned.m16n8k16.row.col.f32.bf16.bf16.f32 "
        "{%0,%1,%2,%3}, {%4,%5,%6,%7}, {%8,%9}, {%0,%1,%2,%3};"
        : "+f"(d[0]), "+f"(d[1]), "+f"(d[2]), "+f"(d[3])
        : "r"(a[0]), "r"(a[1]), "r"(a[2]), "r"(a[3]), "r"(b[0]), "r"(b[1]));
}

// ---------------------------------------------------------------------------
// conv_x: fp32 -> bf16, ||x||.  One warp per row.
// ---------------------------------------------------------------------------
__global__ void conv_x_kernel(const float* __restrict__ x) {
    int row = (blockIdx.x * blockDim.x + threadIdx.x) >> 5;
    int lane = threadIdx.x & 31;
    if (row >= N_ROWS) return;
    const float4* src = reinterpret_cast<const float4*>(x + (size_t)row * DDIM);
    uint4* dst = reinterpret_cast<uint4*>(g_xb + (size_t)row * DDIM);
    float s = 0.f;
#pragma unroll
    for (int j = 0; j < 2; j++) {
        __nv_bfloat162 h[4];
        float4 v0 = src[lane * 4 + j * 2];
        float4 v1 = src[lane * 4 + j * 2 + 1];
        s += v0.x*v0.x + v0.y*v0.y + v0.z*v0.z + v0.w*v0.w;
        s += v1.x*v1.x + v1.y*v1.y + v1.z*v1.z + v1.w*v1.w;
        h[0] = __nv_bfloat162(__float2bfloat16_rn(v0.x), __float2bfloat16_rn(v0.y));
        h[1] = __nv_bfloat162(__float2bfloat16_rn(v0.z), __float2bfloat16_rn(v0.w));
        h[2] = __nv_bfloat162(__float2bfloat16_rn(v1.x), __float2bfloat16_rn(v1.y));
        h[3] = __nv_bfloat162(__float2bfloat16_rn(v1.z), __float2bfloat16_rn(v1.w));
        dst[lane * 2 + j] = *reinterpret_cast<uint4*>(h);
    }
#pragma unroll
    for (int off = 16; off; off >>= 1) s += __shfl_xor_sync(0xFFFFFFFFu, s, off);
    if (lane == 0) g_xnorm[row] = sqrtf(s);
}

__global__ void conv_e_kernel(const float* __restrict__ e) {
    int row = (blockIdx.x * blockDim.x + threadIdx.x) >> 5;
    int lane = threadIdx.x & 31;
    if (row >= K_CODES) return;
    const float4* src = reinterpret_cast<const float4*>(e + (size_t)row * DDIM);
    uint4* dst = reinterpret_cast<uint4*>(g_eb + (size_t)row * DDIM);
    float s = 0.f;
#pragma unroll
    for (int j = 0; j < 2; j++) {
        __nv_bfloat162 h[4];
        float4 v0 = src[lane * 4 + j * 2];
        float4 v1 = src[lane * 4 + j * 2 + 1];
        s += v0.x*v0.x + v0.y*v0.y + v0.z*v0.z + v0.w*v0.w;
        s += v1.x*v1.x + v1.y*v1.y + v1.z*v1.z + v1.w*v1.w;
        h[0] = __nv_bfloat162(__float2bfloat16_rn(v0.x), __float2bfloat16_rn(v0.y));
        h[1] = __nv_bfloat162(__float2bfloat16_rn(v0.z), __float2bfloat16_rn(v0.w));
        h[2] = __nv_bfloat162(__float2bfloat16_rn(v1.x), __float2bfloat16_rn(v1.y));
        h[3] = __nv_bfloat162(__float2bfloat16_rn(v1.z), __float2bfloat16_rn(v1.w));
        dst[lane * 2 + j] = *reinterpret_cast<uint4*>(h);
    }
#pragma unroll
    for (int off = 16; off; off >>= 1) s += __shfl_xor_sync(0xFFFFFFFFu, s, off);
    if (lane == 0) {
        g_bias[row] = -0.5f * s;
        atomicMax(&g_emax2, __float_as_int(s));
    }
}

// ---------------------------------------------------------------------------
// GEMM: ldmatrix mainloop; epilogue stores bf16(score + bias).
// ---------------------------------------------------------------------------
extern __shared__ char smem_g[];

__device__ __forceinline__ void gemm_issue(uint32_t smb, int stage, int row0, int col0,
                                           int chunk, int tid) {
    const int d0 = chunk * BKH;
    const uint32_t st = smb + stage * STAGE_B;
#pragma unroll
    for (int it = 0; it < 6; it++) {
        int i = tid + it * 256;
        int r = i >> 2, c = i & 3;
        if (r < BM) {
            cp16(st + r * ROWSTR_B + c * 16, g_xb + (size_t)(row0 + r) * DDIM + d0 + c * 8);
        } else {
            int r2 = r - BM;
            cp16(st + BM * ROWSTR_B + r2 * ROWSTR_B + c * 16,
                 g_eb + (size_t)(col0 + r2) * DDIM + d0 + c * 8);
        }
    }
}

__global__ __launch_bounds__(256, 1) void gemm_kernel() {
    const int tid = threadIdx.x;
    const int lane = tid & 31;
    const int wid = tid >> 5;
    const int wm = wid >> 2;
    const int wn = wid & 3;
    const int g = lane >> 2;
    const int q = lane & 3;
    const int col0 = blockIdx.x * BN;
    const int row0 = blockIdx.y * BM;
    const uint32_t smb = smem_u32(smem_g);

    // ldmatrix per-lane address components
    const int a_row = wm * 64 + (lane & 15);            // + mt*16
    const int a_col = (lane >> 4) << 4;                 // 0 or 16 bytes; + s*32
    const int b_row = wn * 64 + (lane & 7) + ((lane & 16) ? 8 : 0);  // + ntp*16
    const int b_col = (lane & 8) ? 16 : 0;              // + s*32

    float acc[4][8][4];
#pragma unroll
    for (int mt = 0; mt < 4; mt++)
#pragma unroll
        for (int nt = 0; nt < 8; nt++)
#pragma unroll
            for (int c = 0; c < 4; c++) acc[mt][nt][c] = 0.f;

    gemm_issue(smb, 0, row0, col0, 0, tid); CP_COMMIT();
    gemm_issue(smb, 1, row0, col0, 1, tid); CP_COMMIT();

    for (int ch = 0; ch < NCHUNK; ch++) {
        if (ch + 2 < NCHUNK) gemm_issue(smb, (ch + 2) % NSTAGE, row0, col0, ch + 2, tid);
        CP_COMMIT();
        CP_WAIT2();
        __syncthreads();

        const uint32_t sa_b = smb + (ch % NSTAGE) * STAGE_B;
        const uint32_t sb_b = sa_b + BM * ROWSTR_B;
        const uint32_t a_base = sa_b + a_row * ROWSTR_B + a_col;
        const uint32_t b_base = sb_b + b_row * ROWSTR_B + b_col;

#pragma unroll
        for (int s = 0; s < 2; s++) {
            const int sc32 = s * 32;
            uint32_t a[4][4], b[4][4];
#pragma unroll
            for (int mt = 0; mt < 4; mt++)
                ldsm4(a[mt], a_base + mt * (16 * ROWSTR_B) + sc32);
#pragma unroll
            for (int ntp = 0; ntp < 4; ntp++)
                ldsm4(b[ntp], b_base + ntp * (16 * ROWSTR_B) + sc32);
#pragma unroll
            for (int mt = 0; mt < 4; mt++)
#pragma unroll
                for (int ntp = 0; ntp < 4; ntp++) {
                    mma_bf16(acc[mt][2 * ntp],     a[mt], &b[ntp][0]);
                    mma_bf16(acc[mt][2 * ntp + 1], a[mt], &b[ntp][2]);
                }
        }
        __syncthreads();
    }

    // epilogue: fold bias, store bf16 scores
    float bc0[8], bc1[8];
#pragma unroll
    for (int nt = 0; nt < 8; nt++) {
        int c = col0 + wn * 64 + nt * 8 + q * 2;
        bc0[nt] = __ldg(&g_bias[c]);
        bc1[nt] = __ldg(&g_bias[c + 1]);
    }
#pragma unroll
    for (int mt = 0; mt < 4; mt++) {
        int r = row0 + wm * 64 + mt * 16 + g;
#pragma unroll
        for (int nt = 0; nt < 8; nt++) {
            int c2 = (col0 >> 1) + wn * 32 + nt * 4 + q;
            g_sc2[(size_t)r * (K_CODES / 2) + c2] =
                __nv_bfloat162(__float2bfloat16_rn(acc[mt][nt][0] + bc0[nt]),
                               __float2bfloat16_rn(acc[mt][nt][1] + bc1[nt]));
            g_sc2[(size_t)(r + 8) * (K_CODES / 2) + c2] =
                __nv_bfloat162(__float2bfloat16_rn(acc[mt][nt][2] + bc0[nt]),
                               __float2bfloat16_rn(acc[mt][nt][3] + bc1[nt]));
        }
    }
}

// ---------------------------------------------------------------------------
// Select + gather: warp per row. bf16-SIMD max scan -> hge2 candidate filter
// -> exact fp32 rescore -> write output row + index.
// ---------------------------------------------------------------------------
__global__ __launch_bounds__(256) void select_kernel(const float* __restrict__ x,
                                                     const float* __restrict__ embed,
                                                     float* __restrict__ out, int write_ind) {
    __shared__ int cnt[8];
    __shared__ int cands[8][MAXCAND];

    const int wrow = threadIdx.x >> 5;
    const int row = blockIdx.x * 8 + wrow;
    const int lane = threadIdx.x & 31;
    if (row >= N_ROWS) return;

    if (lane == 0) cnt[wrow] = 0;
    __syncwarp();

    const float4* x4 = reinterpret_cast<const float4*>(x + (size_t)row * DDIM);
    float4 xv[4];
#pragma unroll
    for (int j = 0; j < 4; j++) xv[j] = x4[lane + 32 * j];

    const uint4* s16 = reinterpret_cast<const uint4*>(g_sc2 + (size_t)row * (K_CODES / 2));

    // pass 1: bf16 SIMD row max (scores already include bias)
    __nv_bfloat162 mm2 = __float2bfloat162_rn(-CUDART_INF_F);
#pragma unroll 4
    for (int j = 0; j < 32; j++) {
        uint4 u = s16[lane + 32 * j];
        __nv_bfloat162 p0 = *reinterpret_cast<__nv_bfloat162*>(&u.x);
        __nv_bfloat162 p1 = *reinterpret_cast<__nv_bfloat162*>(&u.y);
        __nv_bfloat162 p2 = *reinterpret_cast<__nv_bfloat162*>(&u.z);
        __nv_bfloat162 p3 = *reinterpret_cast<__nv_bfloat162*>(&u.w);
        mm2 = __hmax2(mm2, __hmax2(__hmax2(p0, p1), __hmax2(p2, p3)));
    }
    float m = fmaxf(__bfloat162float(mm2.x), __bfloat162float(mm2.y));
#pragma unroll
    for (int off = 16; off; off >>= 1) m = fmaxf(m, __shfl_xor_sync(0xFFFFFFFFu, m, off));

    const float margin = 0.02f * g_xnorm[row] * sqrtf(__int_as_float(g_emax2)) + 1.0f;
    const float thr = m - margin;
    const __nv_bfloat16 thr_b = __float2bfloat16_rd(thr);
    const __nv_bfloat162 thr2 = __nv_bfloat162(thr_b, thr_b);

    // pass 2: candidate filter (L1-hot reread)
    for (int j = 0; j < 32; j++) {
        const int i = lane + 32 * j;
        uint4 u = s16[i];
#pragma unroll
        for (int w = 0; w < 4; w++) {
            uint32_t uw = (&u.x)[w];
            __nv_bfloat162 v = *reinterpret_cast<__nv_bfloat162*>(&uw);
            __nv_bfloat162 ge = __hge2(v, thr2);
            if (*reinterpret_cast<uint32_t*>(&ge) != 0u) {
                float2 p = __bfloat1622float2(v);
                if (p.x >= thr) {
                    int pos = atomicAdd(&cnt[wrow], 1);
                    if (pos < MAXCAND) cands[wrow][pos] = i * 8 + w * 2;
                }
                if (p.y >= thr) {
                    int pos = atomicAdd(&cnt[wrow], 1);
                    if (pos < MAXCAND) cands[wrow][pos] = i * 8 + w * 2 + 1;
                }
            }
        }
    }
    __syncwarp();
    const int n = cnt[wrow];

    float best = -CUDART_INF_F;
    int bi = K_CODES;

    if (n <= MAXCAND) {
        for (int ci = 0; ci < n; ci++) {
            int k = cands[wrow][ci];
            const float4* e4 = reinterpret_cast<const float4*>(embed + (size_t)k * DDIM);
            float s = 0.f;
#pragma unroll
            for (int j = 0; j < 4; j++) {
                float4 ev = e4[lane + 32 * j];
                s += xv[j].x * ev.x + xv[j].y * ev.y + xv[j].z * ev.z + xv[j].w * ev.w;
            }
#pragma unroll
            for (int off = 16; off; off >>= 1) s += __shfl_xor_sync(0xFFFFFFFFu, s, off);
            float v = s + g_bias[k];
            if (v > best || (v == best && k < bi)) { best = v; bi = k; }
        }
    } else {
        // overflow fallback: exact full scan, lane-parallel
        for (int k = lane; k < K_CODES; k += 32) {
            const float4* e4 = reinterpret_cast<const float4*>(embed + (size_t)k * DDIM);
            float s = 0.f;
            for (int j = 0; j < DDIM / 4; j++) {
                float4 ev = e4[j];
                float4 xw = x4[j];
                s += xw.x * ev.x + xw.y * ev.y + xw.z * ev.z + xw.w * ev.w;
            }
            float v = s + g_bias[k];
            if (v > best || (v == best && k < bi)) { best = v; bi = k; }
        }
#pragma unroll
        for (int off = 16; off; off >>= 1) {
            float ov = __shfl_xor_sync(0xFFFFFFFFu, best, off);
            int   oi = __shfl_xor_sync(0xFFFFFFFFu, bi, off);
            if (ov > best || (ov == best && oi < bi)) { best = ov; bi = oi; }
        }
    }

    bi = __shfl_sync(0xFFFFFFFFu, bi, 0);

    // fused gather
    const float4* src = reinterpret_cast<const float4*>(embed + (size_t)bi * DDIM);
    float4* dst = reinterpret_cast<float4*>(out + (size_t)row * DDIM);
#pragma unroll
    for (int j = 0; j < 4; j++) dst[lane + 32 * j] = src[lane + 32 * j];
    if (write_ind && lane == 0) out[(size_t)N_ROWS * DDIM + row] = (float)bi;
}

// ---------------------------------------------------------------------------
extern "C" void kernel_launch(void* const* d_in, const int* in_sizes, int n_in,
                              void* d_out, int out_size) {
    const float* x     = (const float*)d_in[0];
    const float* embed = (const float*)d_in[1];
    float* out = (float*)d_out;
    (void)in_sizes; (void)n_in;
    int write_ind = (out_size >= N_ROWS * DDIM + N_ROWS) ? 1 : 0;

    cudaFuncSetAttribute(gemm_kernel, cudaFuncAttributeMaxDynamicSharedMemorySize, SMEM_GEMM);

    conv_x_kernel<<<N_ROWS / 8, 256>>>(x);
    conv_e_kernel<<<K_CODES / 8, 256>>>(embed);
    gemm_kernel<<<dim3(K_CODES / BN, N_ROWS / BM), 256, SMEM_GEMM>>>();
    select_kernel<<<N_ROWS / 8, 256>>>(x, embed, out, write_ind);
}

// round 10
// speedup vs baseline: 65.7754x; 1.0930x over previous
#include <cuda_runtime.h>
#include <cuda_bf16.h>
#include <math_constants.h>
#include <cstdint>

#define DDIM    512
#define N_ROWS  16384
#define K_CODES 8192

// ---- GEMM tiling ----
#define BM      128
#define BN      256
#define BKH     32
#define NCHUNK  (DDIM / BKH)  // 16
#define NTILE   (K_CODES / BN) // 32
#define ROWSTR_B 80           // 32 halves + pad -> ldmatrix bank-permutation friendly
#define STAGE_B ((BM + BN) * ROWSTR_B)   // 30720
#define NSTAGE  3
#define SMEM_GEMM (NSTAGE * STAGE_B)     // 92160

#define MAXCAND 64

// ---- device scratch (allocation-free) ----
__device__ __nv_bfloat16 g_xb[(size_t)N_ROWS * DDIM];
__device__ __nv_bfloat16 g_eb[(size_t)K_CODES * DDIM];
__device__ __align__(16) float g_bias[K_CODES];        // -0.5*||e||^2
__device__ float g_xnorm[N_ROWS];
__device__ int   g_emax2;                               // max ||e||^2 (float bits); idempotent
__device__ __nv_bfloat162 g_sc2[(size_t)N_ROWS * (K_CODES / 2)];  // scores WITH bias folded
__device__ uint32_t g_tilemax[(size_t)N_ROWS * NTILE];  // fenc(per-row per-tile fp32 max)

// ---------------------------------------------------------------------------
__device__ __forceinline__ uint32_t smem_u32(const void* p) {
    uint32_t a;
    asm("{ .reg .u64 t; cvta.to.shared.u64 t, %1; cvt.u32.u64 %0, t; }" : "=r"(a) : "l"(p));
    return a;
}
__device__ __forceinline__ void cp16(uint32_t dst, const void* src) {
    asm volatile("cp.async.cg.shared.global [%0], [%1], 16;" :: "r"(dst), "l"(src) : "memory");
}
#define CP_COMMIT() asm volatile("cp.async.commit_group;" ::: "memory")
#define CP_WAIT2()  asm volatile("cp.async.wait_group 2;" ::: "memory")

__device__ __forceinline__ void ldsm4(uint32_t* r, uint32_t addr) {
    asm volatile("ldmatrix.sync.aligned.m8n8.x4.shared.b16 {%0,%1,%2,%3}, [%4];"
                 : "=r"(r[0]), "=r"(r[1]), "=r"(r[2]), "=r"(r[3]) : "r"(addr));
}
__device__ __forceinline__ void mma_bf16(float* d, const uint32_t* a, const uint32_t* b) {
    asm volatile(
        "mma.sync.aligned.m16n8k16.row.col.f32.bf16.bf16.f32 "
        "{%0,%1,%2,%3}, {%4,%5,%6,%7}, {%8,%9}, {%0,%1,%2,%3};"
        : "+f"(d[0]), "+f"(d[1]), "+f"(d[2]), "+f"(d[3])
        : "r"(a[0]), "r"(a[1]), "r"(a[2]), "r"(a[3]), "r"(b[0]), "r"(b[1]));
}

// order-preserving float<->uint for atomicMax
__device__ __forceinline__ uint32_t fenc(float f) {
    uint32_t u = __float_as_uint(f);
    return (u & 0x80000000u) ? ~u : (u | 0x80000000u);
}
__device__ __forceinline__ float fdec(uint32_t u) {
    return __uint_as_float((u & 0x80000000u) ? (u ^ 0x80000000u) : ~u);
}

// ---------------------------------------------------------------------------
// conv_x: fp32 -> bf16, ||x||, reset tilemax (graph-replay safe). Warp/row.
// ---------------------------------------------------------------------------
__global__ void conv_x_kernel(const float* __restrict__ x) {
    int row = (blockIdx.x * blockDim.x + threadIdx.x) >> 5;
    int lane = threadIdx.x & 31;
    if (row >= N_ROWS) return;
    const float4* src = reinterpret_cast<const float4*>(x + (size_t)row * DDIM);
    uint4* dst = reinterpret_cast<uint4*>(g_xb + (size_t)row * DDIM);
    float s = 0.f;
#pragma unroll
    for (int j = 0; j < 2; j++) {
        __nv_bfloat162 h[4];
        float4 v0 = src[lane * 4 + j * 2];
        float4 v1 = src[lane * 4 + j * 2 + 1];
        s += v0.x*v0.x + v0.y*v0.y + v0.z*v0.z + v0.w*v0.w;
        s += v1.x*v1.x + v1.y*v1.y + v1.z*v1.z + v1.w*v1.w;
        h[0] = __nv_bfloat162(__float2bfloat16_rn(v0.x), __float2bfloat16_rn(v0.y));
        h[1] = __nv_bfloat162(__float2bfloat16_rn(v0.z), __float2bfloat16_rn(v0.w));
        h[2] = __nv_bfloat162(__float2bfloat16_rn(v1.x), __float2bfloat16_rn(v1.y));
        h[3] = __nv_bfloat162(__float2bfloat16_rn(v1.z), __float2bfloat16_rn(v1.w));
        dst[lane * 2 + j] = *reinterpret_cast<uint4*>(h);
    }
    g_tilemax[(size_t)row * NTILE + lane] = 0u;   // 32 lanes x 32 tiles; 0 == fenc(-inf)
#pragma unroll
    for (int off = 16; off; off >>= 1) s += __shfl_xor_sync(0xFFFFFFFFu, s, off);
    if (lane == 0) g_xnorm[row] = sqrtf(s);
}

__global__ void conv_e_kernel(const float* __restrict__ e) {
    int row = (blockIdx.x * blockDim.x + threadIdx.x) >> 5;
    int lane = threadIdx.x & 31;
    if (row >= K_CODES) return;
    const float4* src = reinterpret_cast<const float4*>(e + (size_t)row * DDIM);
    uint4* dst = reinterpret_cast<uint4*>(g_eb + (size_t)row * DDIM);
    float s = 0.f;
#pragma unroll
    for (int j = 0; j < 2; j++) {
        __nv_bfloat162 h[4];
        float4 v0 = src[lane * 4 + j * 2];
        float4 v1 = src[lane * 4 + j * 2 + 1];
        s += v0.x*v0.x + v0.y*v0.y + v0.z*v0.z + v0.w*v0.w;
        s += v1.x*v1.x + v1.y*v1.y + v1.z*v1.z + v1.w*v1.w;
        h[0] = __nv_bfloat162(__float2bfloat16_rn(v0.x), __float2bfloat16_rn(v0.y));
        h[1] = __nv_bfloat162(__float2bfloat16_rn(v0.z), __float2bfloat16_rn(v0.w));
        h[2] = __nv_bfloat162(__float2bfloat16_rn(v1.x), __float2bfloat16_rn(v1.y));
        h[3] = __nv_bfloat162(__float2bfloat16_rn(v1.z), __float2bfloat16_rn(v1.w));
        dst[lane * 2 + j] = *reinterpret_cast<uint4*>(h);
    }
#pragma unroll
    for (int off = 16; off; off >>= 1) s += __shfl_xor_sync(0xFFFFFFFFu, s, off);
    if (lane == 0) {
        g_bias[row] = -0.5f * s;
        atomicMax(&g_emax2, __float_as_int(s));
    }
}

// ---------------------------------------------------------------------------
// GEMM: ldmatrix mainloop; epilogue stores bf16(score+bias) + per-row tile max.
// ---------------------------------------------------------------------------
extern __shared__ char smem_g[];

__device__ __forceinline__ void gemm_issue(uint32_t smb, int stage, int row0, int col0,
                                           int chunk, int tid) {
    const int d0 = chunk * BKH;
    const uint32_t st = smb + stage * STAGE_B;
#pragma unroll
    for (int it = 0; it < 6; it++) {
        int i = tid + it * 256;
        int r = i >> 2, c = i & 3;
        if (r < BM) {
            cp16(st + r * ROWSTR_B + c * 16, g_xb + (size_t)(row0 + r) * DDIM + d0 + c * 8);
        } else {
            int r2 = r - BM;
            cp16(st + BM * ROWSTR_B + r2 * ROWSTR_B + c * 16,
                 g_eb + (size_t)(col0 + r2) * DDIM + d0 + c * 8);
        }
    }
}

__global__ __launch_bounds__(256, 1) void gemm_kernel() {
    const int tid = threadIdx.x;
    const int lane = tid & 31;
    const int wid = tid >> 5;
    const int wm = wid >> 2;
    const int wn = wid & 3;
    const int g = lane >> 2;
    const int q = lane & 3;
    const int col0 = blockIdx.x * BN;
    const int row0 = blockIdx.y * BM;
    const uint32_t smb = smem_u32(smem_g);

    const int a_row = wm * 64 + (lane & 15);
    const int a_col = (lane >> 4) << 4;
    const int b_row = wn * 64 + (lane & 7) + ((lane & 16) ? 8 : 0);
    const int b_col = (lane & 8) ? 16 : 0;

    float acc[4][8][4];
#pragma unroll
    for (int mt = 0; mt < 4; mt++)
#pragma unroll
        for (int nt = 0; nt < 8; nt++)
#pragma unroll
            for (int c = 0; c < 4; c++) acc[mt][nt][c] = 0.f;

    gemm_issue(smb, 0, row0, col0, 0, tid); CP_COMMIT();
    gemm_issue(smb, 1, row0, col0, 1, tid); CP_COMMIT();

    for (int ch = 0; ch < NCHUNK; ch++) {
        if (ch + 2 < NCHUNK) gemm_issue(smb, (ch + 2) % NSTAGE, row0, col0, ch + 2, tid);
        CP_COMMIT();
        CP_WAIT2();
        __syncthreads();

        const uint32_t sa_b = smb + (ch % NSTAGE) * STAGE_B;
        const uint32_t sb_b = sa_b + BM * ROWSTR_B;
        const uint32_t a_base = sa_b + a_row * ROWSTR_B + a_col;
        const uint32_t b_base = sb_b + b_row * ROWSTR_B + b_col;

#pragma unroll
        for (int s = 0; s < 2; s++) {
            const int sc32 = s * 32;
            uint32_t a[4][4], b[4][4];
#pragma unroll
            for (int mt = 0; mt < 4; mt++)
                ldsm4(a[mt], a_base + mt * (16 * ROWSTR_B) + sc32);
#pragma unroll
            for (int ntp = 0; ntp < 4; ntp++)
                ldsm4(b[ntp], b_base + ntp * (16 * ROWSTR_B) + sc32);
#pragma unroll
            for (int mt = 0; mt < 4; mt++)
#pragma unroll
                for (int ntp = 0; ntp < 4; ntp++) {
                    mma_bf16(acc[mt][2 * ntp],     a[mt], &b[ntp][0]);
                    mma_bf16(acc[mt][2 * ntp + 1], a[mt], &b[ntp][2]);
                }
        }
        __syncthreads();
    }

    // epilogue: fold bias, store bf16 scores, per-row tile max sidecar
    float bc0[8], bc1[8];
#pragma unroll
    for (int nt = 0; nt < 8; nt++) {
        int c = col0 + wn * 64 + nt * 8 + q * 2;
        bc0[nt] = __ldg(&g_bias[c]);
        bc1[nt] = __ldg(&g_bias[c + 1]);
    }
#pragma unroll
    for (int mt = 0; mt < 4; mt++) {
        int r = row0 + wm * 64 + mt * 16 + g;
        float m1 = -CUDART_INF_F, m2 = -CUDART_INF_F;
#pragma unroll
        for (int nt = 0; nt < 8; nt++) {
            float v0 = acc[mt][nt][0] + bc0[nt];
            float v1 = acc[mt][nt][1] + bc1[nt];
            float v2 = acc[mt][nt][2] + bc0[nt];
            float v3 = acc[mt][nt][3] + bc1[nt];
            m1 = fmaxf(m1, fmaxf(v0, v1));
            m2 = fmaxf(m2, fmaxf(v2, v3));
            int c2 = (col0 >> 1) + wn * 32 + nt * 4 + q;
            g_sc2[(size_t)r * (K_CODES / 2) + c2] =
                __nv_bfloat162(__float2bfloat16_rn(v0), __float2bfloat16_rn(v1));
            g_sc2[(size_t)(r + 8) * (K_CODES / 2) + c2] =
                __nv_bfloat162(__float2bfloat16_rn(v2), __float2bfloat16_rn(v3));
        }
        m1 = fmaxf(m1, __shfl_xor_sync(0xFFFFFFFFu, m1, 1));
        m1 = fmaxf(m1, __shfl_xor_sync(0xFFFFFFFFu, m1, 2));
        m2 = fmaxf(m2, __shfl_xor_sync(0xFFFFFFFFu, m2, 1));
        m2 = fmaxf(m2, __shfl_xor_sync(0xFFFFFFFFu, m2, 2));
        if (q == 0) {
            atomicMax(&g_tilemax[(size_t)r * NTILE + blockIdx.x], fenc(m1));
            atomicMax(&g_tilemax[(size_t)(r + 8) * NTILE + blockIdx.x], fenc(m2));
        }
    }
}

// ---------------------------------------------------------------------------
// Select + gather: warp per row. tilemax scan -> ballot tiles -> candidate
// filter on surviving tiles -> exact fp32 rescore -> output.
// ---------------------------------------------------------------------------
__global__ __launch_bounds__(256) void select_kernel(const float* __restrict__ x,
                                                     const float* __restrict__ embed,
                                                     float* __restrict__ out, int write_ind) {
    __shared__ int cnt[8];
    __shared__ int cands[8][MAXCAND];

    const int wrow = threadIdx.x >> 5;
    const int row = blockIdx.x * 8 + wrow;
    const int lane = threadIdx.x & 31;
    if (row >= N_ROWS) return;

    if (lane == 0) cnt[wrow] = 0;
    __syncwarp();

    const float4* x4 = reinterpret_cast<const float4*>(x + (size_t)row * DDIM);
    float4 xv[4];
#pragma unroll
    for (int j = 0; j < 4; j++) xv[j] = x4[lane + 32 * j];

    // per-tile fp32 maxima (one per lane) -> global max
    const float tv = fdec(g_tilemax[(size_t)row * NTILE + lane]);
    float gmax = tv;
#pragma unroll
    for (int off = 16; off; off >>= 1) gmax = fmaxf(gmax, __shfl_xor_sync(0xFFFFFFFFu, gmax, off));

    const float margin = 0.02f * g_xnorm[row] * sqrtf(__int_as_float(g_emax2)) + 1.0f;
    const float thr = gmax - margin;

    unsigned tmask = __ballot_sync(0xFFFFFFFFu, tv >= thr);

    const uint4* s16 = reinterpret_cast<const uint4*>(g_sc2 + (size_t)row * (K_CODES / 2));

    // scan only surviving tiles (each tile: 32 lanes x 1 uint4 = 256 scores)
    while (tmask) {
        const int t = __ffs(tmask) - 1;
        tmask &= tmask - 1;
        uint4 u = s16[t * 32 + lane];
#pragma unroll
        for (int w = 0; w < 4; w++) {
            uint32_t uw = (&u.x)[w];
            float2 p = __bfloat1622float2(*reinterpret_cast<__nv_bfloat162*>(&uw));
            if (p.x >= thr) {
                int pos = atomicAdd(&cnt[wrow], 1);
                if (pos < MAXCAND) cands[wrow][pos] = t * 256 + lane * 8 + w * 2;
            }
            if (p.y >= thr) {
                int pos = atomicAdd(&cnt[wrow], 1);
                if (pos < MAXCAND) cands[wrow][pos] = t * 256 + lane * 8 + w * 2 + 1;
            }
        }
    }
    __syncwarp();
    const int n = cnt[wrow];

    float best = -CUDART_INF_F;
    int bi = K_CODES;

    if (n <= MAXCAND) {
        for (int ci = 0; ci < n; ci++) {
            int k = cands[wrow][ci];
            const float4* e4 = reinterpret_cast<const float4*>(embed + (size_t)k * DDIM);
            float s = 0.f;
#pragma unroll
            for (int j = 0; j < 4; j++) {
                float4 ev = e4[lane + 32 * j];
                s += xv[j].x * ev.x + xv[j].y * ev.y + xv[j].z * ev.z + xv[j].w * ev.w;
            }
#pragma unroll
            for (int off = 16; off; off >>= 1) s += __shfl_xor_sync(0xFFFFFFFFu, s, off);
            float v = s + g_bias[k];
            if (v > best || (v == best && k < bi)) { best = v; bi = k; }
        }
    } else {
        // overflow fallback: exact full scan, lane-parallel
        for (int k = lane; k < K_CODES; k += 32) {
            const float4* e4 = reinterpret_cast<const float4*>(embed + (size_t)k * DDIM);
            float s = 0.f;
            for (int j = 0; j < DDIM / 4; j++) {
                float4 ev = e4[j];
                float4 xw = x4[j];
                s += xw.x * ev.x + xw.y * ev.y + xw.z * ev.z + xw.w * ev.w;
            }
            float v = s + g_bias[k];
            if (v > best || (v == best && k < bi)) { best = v; bi = k; }
        }
#pragma unroll
        for (int off = 16; off; off >>= 1) {
            float ov = __shfl_xor_sync(0xFFFFFFFFu, best, off);
            int   oi = __shfl_xor_sync(0xFFFFFFFFu, bi, off);
            if (ov > best || (ov == best && oi < bi)) { best = ov; bi = oi; }
        }
    }

    bi = __shfl_sync(0xFFFFFFFFu, bi, 0);

    // fused gather
    const float4* src = reinterpret_cast<const float4*>(embed + (size_t)bi * DDIM);
    float4* dst = reinterpret_cast<float4*>(out + (size_t)row * DDIM);
#pragma unroll
    for (int j = 0; j < 4; j++) dst[lane + 32 * j] = src[lane + 32 * j];
    if (write_ind && lane == 0) out[(size_t)N_ROWS * DDIM + row] = (float)bi;
}

// ---------------------------------------------------------------------------
extern "C" void kernel_launch(void* const* d_in, const int* in_sizes, int n_in,
                              void* d_out, int out_size) {
    const float* x     = (const float*)d_in[0];
    const float* embed = (const float*)d_in[1];
    float* out = (float*)d_out;
    (void)in_sizes; (void)n_in;
    int write_ind = (out_size >= N_ROWS * DDIM + N_ROWS) ? 1 : 0;

    cudaFuncSetAttribute(gemm_kernel, cudaFuncAttributeMaxDynamicSharedMemorySize, SMEM_GEMM);

    conv_x_kernel<<<N_ROWS / 8, 256>>>(x);
    conv_e_kernel<<<K_CODES / 8, 256>>>(embed);
    gemm_kernel<<<dim3(K_CODES / BN, N_ROWS / BM), 256, SMEM_GEMM>>>();
    select_kernel<<<N_ROWS / 8, 256>>>(x, embed, out, write_ind);
}

// round 11
// speedup vs baseline: 77.2482x; 1.1744x over previous
#include <cuda_runtime.h>
#include <cuda_bf16.h>
#include <math_constants.h>
#include <cstdint>

#define DDIM    512
#define N_ROWS  16384
#define K_CODES 8192

// ---- GEMM tiling ----
#define BM      128
#define BN      256
#define BKH     64            // halves per chunk = full 128B rows
#define NCHUNK  (DDIM / BKH)  // 8
#define NTILE   (K_CODES / BN) // 32
#define ROWSTR_B 144          // 64 halves + 8 pad -> stride 9 (16B units), conflict-free
#define STAGE_B ((BM + BN) * ROWSTR_B)   // 55296
#define NSTAGE  3
#define SMEM_GEMM (NSTAGE * STAGE_B)     // 165888

#define MAXCAND 64

// ---- device scratch (allocation-free) ----
__device__ __nv_bfloat16 g_xb[(size_t)N_ROWS * DDIM];
__device__ __nv_bfloat16 g_eb[(size_t)K_CODES * DDIM];
__device__ __align__(16) float g_bias[K_CODES];        // -0.5*||e||^2
__device__ float g_xnorm[N_ROWS];
__device__ int   g_emax2;                               // max ||e||^2 (float bits); idempotent
__device__ __nv_bfloat162 g_sc2[(size_t)N_ROWS * (K_CODES / 2)];  // scores WITH bias folded
__device__ uint32_t g_tilemax[(size_t)N_ROWS * NTILE];  // fenc(per-row per-tile fp32 max)

// ---------------------------------------------------------------------------
__device__ __forceinline__ uint32_t smem_u32(const void* p) {
    uint32_t a;
    asm("{ .reg .u64 t; cvta.to.shared.u64 t, %1; cvt.u32.u64 %0, t; }" : "=r"(a) : "l"(p));
    return a;
}
__device__ __forceinline__ void cp16(uint32_t dst, const void* src) {
    asm volatile("cp.async.cg.shared.global [%0], [%1], 16;" :: "r"(dst), "l"(src) : "memory");
}
#define CP_COMMIT() asm volatile("cp.async.commit_group;" ::: "memory")
#define CP_WAIT1()  asm volatile("cp.async.wait_group 1;" ::: "memory")

__device__ __forceinline__ void ldsm4(uint32_t* r, uint32_t addr) {
    asm volatile("ldmatrix.sync.aligned.m8n8.x4.shared.b16 {%0,%1,%2,%3}, [%4];"
                 : "=r"(r[0]), "=r"(r[1]), "=r"(r[2]), "=r"(r[3]) : "r"(addr));
}
__device__ __forceinline__ void mma_bf16(float* d, const uint32_t* a, const uint32_t* b) {
    asm volatile(
        "mma.sync.aligned.m16n8k16.row.col.f32.bf16.bf16.f32 "
        "{%0,%1,%2,%3}, {%4,%5,%6,%7}, {%8,%9}, {%0,%1,%2,%3};"
        : "+f"(d[0]), "+f"(d[1]), "+f"(d[2]), "+f"(d[3])
        : "r"(a[0]), "r"(a[1]), "r"(a[2]), "r"(a[3]), "r"(b[0]), "r"(b[1]));
}

// order-preserving float<->uint for atomicMax
__device__ __forceinline__ uint32_t fenc(float f) {
    uint32_t u = __float_as_uint(f);
    return (u & 0x80000000u) ? ~u : (u | 0x80000000u);
}
__device__ __forceinline__ float fdec(uint32_t u) {
    return __uint_as_float((u & 0x80000000u) ? (u ^ 0x80000000u) : ~u);
}

// ---------------------------------------------------------------------------
// conv_x: fp32 -> bf16, ||x||, reset tilemax (graph-replay safe). Warp/row.
// ---------------------------------------------------------------------------
__global__ void conv_x_kernel(const float* __restrict__ x) {
    int row = (blockIdx.x * blockDim.x + threadIdx.x) >> 5;
    int lane = threadIdx.x & 31;
    if (row >= N_ROWS) return;
    const float4* src = reinterpret_cast<const float4*>(x + (size_t)row * DDIM);
    uint4* dst = reinterpret_cast<uint4*>(g_xb + (size_t)row * DDIM);
    float s = 0.f;
#pragma unroll
    for (int j = 0; j < 2; j++) {
        __nv_bfloat162 h[4];
        float4 v0 = src[lane * 4 + j * 2];
        float4 v1 = src[lane * 4 + j * 2 + 1];
        s += v0.x*v0.x + v0.y*v0.y + v0.z*v0.z + v0.w*v0.w;
        s += v1.x*v1.x + v1.y*v1.y + v1.z*v1.z + v1.w*v1.w;
        h[0] = __nv_bfloat162(__float2bfloat16_rn(v0.x), __float2bfloat16_rn(v0.y));
        h[1] = __nv_bfloat162(__float2bfloat16_rn(v0.z), __float2bfloat16_rn(v0.w));
        h[2] = __nv_bfloat162(__float2bfloat16_rn(v1.x), __float2bfloat16_rn(v1.y));
        h[3] = __nv_bfloat162(__float2bfloat16_rn(v1.z), __float2bfloat16_rn(v1.w));
        dst[lane * 2 + j] = *reinterpret_cast<uint4*>(h);
    }
    g_tilemax[(size_t)row * NTILE + lane] = 0u;   // 0 == fenc(-inf)
#pragma unroll
    for (int off = 16; off; off >>= 1) s += __shfl_xor_sync(0xFFFFFFFFu, s, off);
    if (lane == 0) g_xnorm[row] = sqrtf(s);
}

__global__ void conv_e_kernel(const float* __restrict__ e) {
    int row = (blockIdx.x * blockDim.x + threadIdx.x) >> 5;
    int lane = threadIdx.x & 31;
    if (row >= K_CODES) return;
    const float4* src = reinterpret_cast<const float4*>(e + (size_t)row * DDIM);
    uint4* dst = reinterpret_cast<uint4*>(g_eb + (size_t)row * DDIM);
    float s = 0.f;
#pragma unroll
    for (int j = 0; j < 2; j++) {
        __nv_bfloat162 h[4];
        float4 v0 = src[lane * 4 + j * 2];
        float4 v1 = src[lane * 4 + j * 2 + 1];
        s += v0.x*v0.x + v0.y*v0.y + v0.z*v0.z + v0.w*v0.w;
        s += v1.x*v1.x + v1.y*v1.y + v1.z*v1.z + v1.w*v1.w;
        h[0] = __nv_bfloat162(__float2bfloat16_rn(v0.x), __float2bfloat16_rn(v0.y));
        h[1] = __nv_bfloat162(__float2bfloat16_rn(v0.z), __float2bfloat16_rn(v0.w));
        h[2] = __nv_bfloat162(__float2bfloat16_rn(v1.x), __float2bfloat16_rn(v1.y));
        h[3] = __nv_bfloat162(__float2bfloat16_rn(v1.z), __float2bfloat16_rn(v1.w));
        dst[lane * 2 + j] = *reinterpret_cast<uint4*>(h);
    }
#pragma unroll
    for (int off = 16; off; off >>= 1) s += __shfl_xor_sync(0xFFFFFFFFu, s, off);
    if (lane == 0) {
        g_bias[row] = -0.5f * s;
        atomicMax(&g_emax2, __float_as_int(s));
    }
}

// ---------------------------------------------------------------------------
// GEMM: ldmatrix mainloop, 8 chunks, ONE barrier per chunk.
// ---------------------------------------------------------------------------
extern __shared__ char smem_g[];

__device__ __forceinline__ void gemm_issue(uint32_t smb, int stage, int row0, int col0,
                                           int chunk, int tid) {
    const int d0 = chunk * BKH;
    const uint32_t st = smb + stage * STAGE_B;
#pragma unroll
    for (int it = 0; it < 12; it++) {              // 384 rows x 8 x 16B / 256 thr
        int i = tid + it * 256;
        int r = i >> 3, c = i & 7;
        if (r < BM) {
            cp16(st + r * ROWSTR_B + c * 16, g_xb + (size_t)(row0 + r) * DDIM + d0 + c * 8);
        } else {
            int r2 = r - BM;
            cp16(st + BM * ROWSTR_B + r2 * ROWSTR_B + c * 16,
                 g_eb + (size_t)(col0 + r2) * DDIM + d0 + c * 8);
        }
    }
}

__global__ __launch_bounds__(256, 1) void gemm_kernel() {
    const int tid = threadIdx.x;
    const int lane = tid & 31;
    const int wid = tid >> 5;
    const int wm = wid >> 2;
    const int wn = wid & 3;
    const int g = lane >> 2;
    const int q = lane & 3;
    const int col0 = blockIdx.x * BN;
    const int row0 = blockIdx.y * BM;
    const uint32_t smb = smem_u32(smem_g);

    const int a_row = wm * 64 + (lane & 15);
    const int a_col = (lane >> 4) << 4;
    const int b_row = wn * 64 + (lane & 7) + ((lane & 16) ? 8 : 0);
    const int b_col = (lane & 8) ? 16 : 0;

    float acc[4][8][4];
#pragma unroll
    for (int mt = 0; mt < 4; mt++)
#pragma unroll
        for (int nt = 0; nt < 8; nt++)
#pragma unroll
            for (int c = 0; c < 4; c++) acc[mt][nt][c] = 0.f;

    gemm_issue(smb, 0, row0, col0, 0, tid); CP_COMMIT();
    gemm_issue(smb, 1, row0, col0, 1, tid); CP_COMMIT();

    for (int ch = 0; ch < NCHUNK; ch++) {
        CP_WAIT1();                      // chunk ch resident (outstanding: ch+1)
        __syncthreads();                 // all warps done reading stage (ch+2)%3 (== ch-1)

        if (ch + 2 < NCHUNK) gemm_issue(smb, (ch + 2) % NSTAGE, row0, col0, ch + 2, tid);
        CP_COMMIT();                     // commit (possibly empty) keeps group counts aligned

        const uint32_t sa_b = smb + (ch % NSTAGE) * STAGE_B;
        const uint32_t sb_b = sa_b + BM * ROWSTR_B;
        const uint32_t a_base = sa_b + a_row * ROWSTR_B + a_col;
        const uint32_t b_base = sb_b + b_row * ROWSTR_B + b_col;

#pragma unroll
        for (int s = 0; s < 4; s++) {    // four k16 steps per 128B chunk
            const int sc32 = s * 32;
            uint32_t a[4][4], b[4][4];
#pragma unroll
            for (int mt = 0; mt < 4; mt++)
                ldsm4(a[mt], a_base + mt * (16 * ROWSTR_B) + sc32);
#pragma unroll
            for (int ntp = 0; ntp < 4; ntp++)
                ldsm4(b[ntp], b_base + ntp * (16 * ROWSTR_B) + sc32);
#pragma unroll
            for (int mt = 0; mt < 4; mt++)
#pragma unroll
                for (int ntp = 0; ntp < 4; ntp++) {
                    mma_bf16(acc[mt][2 * ntp],     a[mt], &b[ntp][0]);
                    mma_bf16(acc[mt][2 * ntp + 1], a[mt], &b[ntp][2]);
                }
        }
    }

    // epilogue: fold bias, store bf16 scores, per-row tile max sidecar
    float bc0[8], bc1[8];
#pragma unroll
    for (int nt = 0; nt < 8; nt++) {
        int c = col0 + wn * 64 + nt * 8 + q * 2;
        bc0[nt] = __ldg(&g_bias[c]);
        bc1[nt] = __ldg(&g_bias[c + 1]);
    }
#pragma unroll
    for (int mt = 0; mt < 4; mt++) {
        int r = row0 + wm * 64 + mt * 16 + g;
        float m1 = -CUDART_INF_F, m2 = -CUDART_INF_F;
#pragma unroll
        for (int nt = 0; nt < 8; nt++) {
            float v0 = acc[mt][nt][0] + bc0[nt];
            float v1 = acc[mt][nt][1] + bc1[nt];
            float v2 = acc[mt][nt][2] + bc0[nt];
            float v3 = acc[mt][nt][3] + bc1[nt];
            m1 = fmaxf(m1, fmaxf(v0, v1));
            m2 = fmaxf(m2, fmaxf(v2, v3));
            int c2 = (col0 >> 1) + wn * 32 + nt * 4 + q;
            g_sc2[(size_t)r * (K_CODES / 2) + c2] =
                __nv_bfloat162(__float2bfloat16_rn(v0), __float2bfloat16_rn(v1));
            g_sc2[(size_t)(r + 8) * (K_CODES / 2) + c2] =
                __nv_bfloat162(__float2bfloat16_rn(v2), __float2bfloat16_rn(v3));
        }
        m1 = fmaxf(m1, __shfl_xor_sync(0xFFFFFFFFu, m1, 1));
        m1 = fmaxf(m1, __shfl_xor_sync(0xFFFFFFFFu, m1, 2));
        m2 = fmaxf(m2, __shfl_xor_sync(0xFFFFFFFFu, m2, 1));
        m2 = fmaxf(m2, __shfl_xor_sync(0xFFFFFFFFu, m2, 2));
        if (q == 0) {
            atomicMax(&g_tilemax[(size_t)r * NTILE + blockIdx.x], fenc(m1));
            atomicMax(&g_tilemax[(size_t)(r + 8) * NTILE + blockIdx.x], fenc(m2));
        }
    }
}

// ---------------------------------------------------------------------------
// Select + gather: warp per row. tilemax -> ballot tiles -> candidate filter
// on surviving tiles -> exact fp32 rescore -> output.
// ---------------------------------------------------------------------------
__global__ __launch_bounds__(256) void select_kernel(const float* __restrict__ x,
                                                     const float* __restrict__ embed,
                                                     float* __restrict__ out, int write_ind) {
    __shared__ int cnt[8];
    __shared__ int cands[8][MAXCAND];

    const int wrow = threadIdx.x >> 5;
    const int row = blockIdx.x * 8 + wrow;
    const int lane = threadIdx.x & 31;
    if (row >= N_ROWS) return;

    if (lane == 0) cnt[wrow] = 0;
    __syncwarp();

    const float4* x4 = reinterpret_cast<const float4*>(x + (size_t)row * DDIM);
    float4 xv[4];
#pragma unroll
    for (int j = 0; j < 4; j++) xv[j] = x4[lane + 32 * j];

    const float tv = fdec(g_tilemax[(size_t)row * NTILE + lane]);
    float gmax = tv;
#pragma unroll
    for (int off = 16; off; off >>= 1) gmax = fmaxf(gmax, __shfl_xor_sync(0xFFFFFFFFu, gmax, off));

    const float margin = 0.02f * g_xnorm[row] * sqrtf(__int_as_float(g_emax2)) + 1.0f;
    const float thr = gmax - margin;

    unsigned tmask = __ballot_sync(0xFFFFFFFFu, tv >= thr);

    const uint4* s16 = reinterpret_cast<const uint4*>(g_sc2 + (size_t)row * (K_CODES / 2));

    while (tmask) {
        const int t = __ffs(tmask) - 1;
        tmask &= tmask - 1;
        uint4 u = s16[t * 32 + lane];
#pragma unroll
        for (int w = 0; w < 4; w++) {
            uint32_t uw = (&u.x)[w];
            float2 p = __bfloat1622float2(*reinterpret_cast<__nv_bfloat162*>(&uw));
            if (p.x >= thr) {
                int pos = atomicAdd(&cnt[wrow], 1);
                if (pos < MAXCAND) cands[wrow][pos] = t * 256 + lane * 8 + w * 2;
            }
            if (p.y >= thr) {
                int pos = atomicAdd(&cnt[wrow], 1);
                if (pos < MAXCAND) cands[wrow][pos] = t * 256 + lane * 8 + w * 2 + 1;
            }
        }
    }
    __syncwarp();
    const int n = cnt[wrow];

    float best = -CUDART_INF_F;
    int bi = K_CODES;

    if (n <= MAXCAND) {
        for (int ci = 0; ci < n; ci++) {
            int k = cands[wrow][ci];
            const float4* e4 = reinterpret_cast<const float4*>(embed + (size_t)k * DDIM);
            float s = 0.f;
#pragma unroll
            for (int j = 0; j < 4; j++) {
                float4 ev = e4[lane + 32 * j];
                s += xv[j].x * ev.x + xv[j].y * ev.y + xv[j].z * ev.z + xv[j].w * ev.w;
            }
#pragma unroll
            for (int off = 16; off; off >>= 1) s += __shfl_xor_sync(0xFFFFFFFFu, s, off);
            float v = s + g_bias[k];
            if (v > best || (v == best && k < bi)) { best = v; bi = k; }
        }
    } else {
        for (int k = lane; k < K_CODES; k += 32) {
            const float4* e4 = reinterpret_cast<const float4*>(embed + (size_t)k * DDIM);
            float s = 0.f;
            for (int j = 0; j < DDIM / 4; j++) {
                float4 ev = e4[j];
                float4 xw = x4[j];
                s += xw.x * ev.x + xw.y * ev.y + xw.z * ev.z + xw.w * ev.w;
            }
            float v = s + g_bias[k];
            if (v > best || (v == best && k < bi)) { best = v; bi = k; }
        }
#pragma unroll
        for (int off = 16; off; off >>= 1) {
            float ov = __shfl_xor_sync(0xFFFFFFFFu, best, off);
            int   oi = __shfl_xor_sync(0xFFFFFFFFu, bi, off);
            if (ov > best || (ov == best && oi < bi)) { best = ov; bi = oi; }
        }
    }

    bi = __shfl_sync(0xFFFFFFFFu, bi, 0);

    const float4* src = reinterpret_cast<const float4*>(embed + (size_t)bi * DDIM);
    float4* dst = reinterpret_cast<float4*>(out + (size_t)row * DDIM);
#pragma unroll
    for (int j = 0; j < 4; j++) dst[lane + 32 * j] = src[lane + 32 * j];
    if (write_ind && lane == 0) out[(size_t)N_ROWS * DDIM + row] = (float)bi;
}

// ---------------------------------------------------------------------------
extern "C" void kernel_launch(void* const* d_in, const int* in_sizes, int n_in,
                              void* d_out, int out_size) {
    const float* x     = (const float*)d_in[0];
    const float* embed = (const float*)d_in[1];
    float* out = (float*)d_out;
    (void)in_sizes; (void)n_in;
    int write_ind = (out_size >= N_ROWS * DDIM + N_ROWS) ? 1 : 0;

    cudaFuncSetAttribute(gemm_kernel, cudaFuncAttributeMaxDynamicSharedMemorySize, SMEM_GEMM);

    conv_x_kernel<<<N_ROWS / 8, 256>>>(x);
    conv_e_kernel<<<K_CODES / 8, 256>>>(embed);
    gemm_kernel<<<dim3(K_CODES / BN, N_ROWS / BM), 256, SMEM_GEMM>>>();
    select_kernel<<<N_ROWS / 8, 256>>>(x, embed, out, write_ind);
}

// round 12
// speedup vs baseline: 83.6489x; 1.0829x over previous
#include <cuda_runtime.h>
#include <cuda_bf16.h>
#include <math_constants.h>
#include <cstdint>

#define DDIM    512
#define N_ROWS  16384
#define K_CODES 8192

// ---- GEMM tiling ----
#define BM      128
#define BN      256
#define BKH     64            // halves per chunk = full 128B rows
#define NCHUNK  (DDIM / BKH)  // 8
#define NTILE   (K_CODES / BN) // 32
#define ROWSTR_B 144          // 64 halves + 8 pad -> stride 9 (16B units), conflict-free
#define STAGE_B ((BM + BN) * ROWSTR_B)   // 55296
#define NSTAGE  3
#define SMEM_GEMM (NSTAGE * STAGE_B)     // 165888

#define MAXCAND 64

// ---- device scratch (allocation-free) ----
__device__ __nv_bfloat16 g_xb[(size_t)N_ROWS * DDIM];
__device__ __nv_bfloat16 g_eb[(size_t)K_CODES * DDIM];
__device__ __align__(16) float g_bias[K_CODES];        // -0.5*||e||^2
__device__ float g_xnorm[N_ROWS];
__device__ int   g_emax2;                               // max ||e||^2 (float bits); idempotent
__device__ __nv_bfloat162 g_sc2[(size_t)N_ROWS * (K_CODES / 2)];  // scores WITH bias folded
__device__ uint32_t g_tilemax[(size_t)N_ROWS * NTILE];  // fenc(per-row per-tile fp32 max)

// ---------------------------------------------------------------------------
__device__ __forceinline__ uint32_t smem_u32(const void* p) {
    uint32_t a;
    asm("{ .reg .u64 t; cvta.to.shared.u64 t, %1; cvt.u32.u64 %0, t; }" : "=r"(a) : "l"(p));
    return a;
}
__device__ __forceinline__ void cp16(uint32_t dst, const void* src) {
    asm volatile("cp.async.cg.shared.global [%0], [%1], 16;" :: "r"(dst), "l"(src) : "memory");
}
#define CP_COMMIT() asm volatile("cp.async.commit_group;" ::: "memory")
#define CP_WAIT1()  asm volatile("cp.async.wait_group 1;" ::: "memory")

__device__ __forceinline__ void ldsm4(uint32_t* r, uint32_t addr) {
    asm volatile("ldmatrix.sync.aligned.m8n8.x4.shared.b16 {%0,%1,%2,%3}, [%4];"
                 : "=r"(r[0]), "=r"(r[1]), "=r"(r[2]), "=r"(r[3]) : "r"(addr));
}
__device__ __forceinline__ void mma_bf16(float* d, const uint32_t* a, const uint32_t* b) {
    asm volatile(
        "mma.sync.aligned.m16n8k16.row.col.f32.bf16.bf16.f32 "
        "{%0,%1,%2,%3}, {%4,%5,%6,%7}, {%8,%9}, {%0,%1,%2,%3};"
        : "+f"(d[0]), "+f"(d[1]), "+f"(d[2]), "+f"(d[3])
        : "r"(a[0]), "r"(a[1]), "r"(a[2]), "r"(a[3]), "r"(b[0]), "r"(b[1]));
}

// order-preserving float<->uint for atomicMax
__device__ __forceinline__ uint32_t fenc(float f) {
    uint32_t u = __float_as_uint(f);
    return (u & 0x80000000u) ? ~u : (u | 0x80000000u);
}
__device__ __forceinline__ float fdec(uint32_t u) {
    return __uint_as_float((u & 0x80000000u) ? (u ^ 0x80000000u) : ~u);
}

// ---------------------------------------------------------------------------
// conv: merged x+e conversion.  Warp w < N_ROWS -> x row; else e row.
// ---------------------------------------------------------------------------
__global__ void conv_kernel(const float* __restrict__ x, const float* __restrict__ e) {
    int w = (blockIdx.x * blockDim.x + threadIdx.x) >> 5;
    int lane = threadIdx.x & 31;
    if (w < N_ROWS) {
        const int row = w;
        const float4* src = reinterpret_cast<const float4*>(x + (size_t)row * DDIM);
        uint4* dst = reinterpret_cast<uint4*>(g_xb + (size_t)row * DDIM);
        float s = 0.f;
#pragma unroll
        for (int j = 0; j < 2; j++) {
            __nv_bfloat162 h[4];
            float4 v0 = src[lane * 4 + j * 2];
            float4 v1 = src[lane * 4 + j * 2 + 1];
            s += v0.x*v0.x + v0.y*v0.y + v0.z*v0.z + v0.w*v0.w;
            s += v1.x*v1.x + v1.y*v1.y + v1.z*v1.z + v1.w*v1.w;
            h[0] = __nv_bfloat162(__float2bfloat16_rn(v0.x), __float2bfloat16_rn(v0.y));
            h[1] = __nv_bfloat162(__float2bfloat16_rn(v0.z), __float2bfloat16_rn(v0.w));
            h[2] = __nv_bfloat162(__float2bfloat16_rn(v1.x), __float2bfloat16_rn(v1.y));
            h[3] = __nv_bfloat162(__float2bfloat16_rn(v1.z), __float2bfloat16_rn(v1.w));
            dst[lane * 2 + j] = *reinterpret_cast<uint4*>(h);
        }
        g_tilemax[(size_t)row * NTILE + lane] = 0u;   // 0 == fenc(-inf); graph-replay safe
#pragma unroll
        for (int off = 16; off; off >>= 1) s += __shfl_xor_sync(0xFFFFFFFFu, s, off);
        if (lane == 0) g_xnorm[row] = sqrtf(s);
    } else if (w < N_ROWS + K_CODES) {
        const int row = w - N_ROWS;
        const float4* src = reinterpret_cast<const float4*>(e + (size_t)row * DDIM);
        uint4* dst = reinterpret_cast<uint4*>(g_eb + (size_t)row * DDIM);
        float s = 0.f;
#pragma unroll
        for (int j = 0; j < 2; j++) {
            __nv_bfloat162 h[4];
            float4 v0 = src[lane * 4 + j * 2];
            float4 v1 = src[lane * 4 + j * 2 + 1];
            s += v0.x*v0.x + v0.y*v0.y + v0.z*v0.z + v0.w*v0.w;
            s += v1.x*v1.x + v1.y*v1.y + v1.z*v1.z + v1.w*v1.w;
            h[0] = __nv_bfloat162(__float2bfloat16_rn(v0.x), __float2bfloat16_rn(v0.y));
            h[1] = __nv_bfloat162(__float2bfloat16_rn(v0.z), __float2bfloat16_rn(v0.w));
            h[2] = __nv_bfloat162(__float2bfloat16_rn(v1.x), __float2bfloat16_rn(v1.y));
            h[3] = __nv_bfloat162(__float2bfloat16_rn(v1.z), __float2bfloat16_rn(v1.w));
            dst[lane * 2 + j] = *reinterpret_cast<uint4*>(h);
        }
#pragma unroll
        for (int off = 16; off; off >>= 1) s += __shfl_xor_sync(0xFFFFFFFFu, s, off);
        if (lane == 0) {
            g_bias[row] = -0.5f * s;
            atomicMax(&g_emax2, __float_as_int(s));
        }
    }
}

// ---------------------------------------------------------------------------
// GEMM: ldmatrix mainloop, 8 chunks, ONE barrier per chunk, cp.async spread
// across the 4 k-steps.
// ---------------------------------------------------------------------------
extern __shared__ char smem_g[];

__device__ __forceinline__ void gemm_issue(uint32_t smb, int stage, int row0, int col0,
                                           int chunk, int tid) {
    const int d0 = chunk * BKH;
    const uint32_t st = smb + stage * STAGE_B;
#pragma unroll
    for (int it = 0; it < 12; it++) {              // 384 rows x 8 x 16B / 256 thr
        int i = tid + it * 256;
        int r = i >> 3, c = i & 7;
        if (r < BM) {
            cp16(st + r * ROWSTR_B + c * 16, g_xb + (size_t)(row0 + r) * DDIM + d0 + c * 8);
        } else {
            int r2 = r - BM;
            cp16(st + BM * ROWSTR_B + r2 * ROWSTR_B + c * 16,
                 g_eb + (size_t)(col0 + r2) * DDIM + d0 + c * 8);
        }
    }
}

__global__ __launch_bounds__(256, 1) void gemm_kernel() {
    const int tid = threadIdx.x;
    const int lane = tid & 31;
    const int wid = tid >> 5;
    const int wm = wid >> 2;
    const int wn = wid & 3;
    const int g = lane >> 2;
    const int q = lane & 3;
    const int col0 = blockIdx.x * BN;
    const int row0 = blockIdx.y * BM;
    const uint32_t smb = smem_u32(smem_g);

    const int a_row = wm * 64 + (lane & 15);
    const int a_col = (lane >> 4) << 4;
    const int b_row = wn * 64 + (lane & 7) + ((lane & 16) ? 8 : 0);
    const int b_col = (lane & 8) ? 16 : 0;

    float acc[4][8][4];
#pragma unroll
    for (int mt = 0; mt < 4; mt++)
#pragma unroll
        for (int nt = 0; nt < 8; nt++)
#pragma unroll
            for (int c = 0; c < 4; c++) acc[mt][nt][c] = 0.f;

    gemm_issue(smb, 0, row0, col0, 0, tid); CP_COMMIT();
    gemm_issue(smb, 1, row0, col0, 1, tid); CP_COMMIT();

    for (int ch = 0; ch < NCHUNK; ch++) {
        CP_WAIT1();                      // chunk ch resident (outstanding: ch+1)
        __syncthreads();                 // all warps done reading stage (ch+2)%3 (== ch-1)

        const bool pf = (ch + 2 < NCHUNK);
        const int  pfd0 = (ch + 2) * BKH;
        const uint32_t pst = smb + ((ch + 2) % NSTAGE) * STAGE_B;

        const uint32_t sa_b = smb + (ch % NSTAGE) * STAGE_B;
        const uint32_t sb_b = sa_b + BM * ROWSTR_B;
        const uint32_t a_base = sa_b + a_row * ROWSTR_B + a_col;
        const uint32_t b_base = sb_b + b_row * ROWSTR_B + b_col;

#pragma unroll
        for (int s = 0; s < 4; s++) {    // four k16 steps per 128B chunk
            if (pf) {                    // 3 of 12 prefetch cp16 per step
#pragma unroll
                for (int j = 0; j < 3; j++) {
                    int i = tid + (s * 3 + j) * 256;
                    int r = i >> 3, c = i & 7;
                    if (r < BM) {
                        cp16(pst + r * ROWSTR_B + c * 16,
                             g_xb + (size_t)(row0 + r) * DDIM + pfd0 + c * 8);
                    } else {
                        int r2 = r - BM;
                        cp16(pst + BM * ROWSTR_B + r2 * ROWSTR_B + c * 16,
                             g_eb + (size_t)(col0 + r2) * DDIM + pfd0 + c * 8);
                    }
                }
            }
            const int sc32 = s * 32;
            uint32_t a[4][4], b[4][4];
#pragma unroll
            for (int mt = 0; mt < 4; mt++)
                ldsm4(a[mt], a_base + mt * (16 * ROWSTR_B) + sc32);
#pragma unroll
            for (int ntp = 0; ntp < 4; ntp++)
                ldsm4(b[ntp], b_base + ntp * (16 * ROWSTR_B) + sc32);
#pragma unroll
            for (int mt = 0; mt < 4; mt++)
#pragma unroll
                for (int ntp = 0; ntp < 4; ntp++) {
                    mma_bf16(acc[mt][2 * ntp],     a[mt], &b[ntp][0]);
                    mma_bf16(acc[mt][2 * ntp + 1], a[mt], &b[ntp][2]);
                }
        }
        CP_COMMIT();                     // one group per chunk (possibly empty)
    }

    // epilogue: fold bias, store bf16 scores, per-row tile max sidecar
    float bc0[8], bc1[8];
#pragma unroll
    for (int nt = 0; nt < 8; nt++) {
        int c = col0 + wn * 64 + nt * 8 + q * 2;
        bc0[nt] = __ldg(&g_bias[c]);
        bc1[nt] = __ldg(&g_bias[c + 1]);
    }
#pragma unroll
    for (int mt = 0; mt < 4; mt++) {
        int r = row0 + wm * 64 + mt * 16 + g;
        float m1 = -CUDART_INF_F, m2 = -CUDART_INF_F;
#pragma unroll
        for (int nt = 0; nt < 8; nt++) {
            float v0 = acc[mt][nt][0] + bc0[nt];
            float v1 = acc[mt][nt][1] + bc1[nt];
            float v2 = acc[mt][nt][2] + bc0[nt];
            float v3 = acc[mt][nt][3] + bc1[nt];
            m1 = fmaxf(m1, fmaxf(v0, v1));
            m2 = fmaxf(m2, fmaxf(v2, v3));
            int c2 = (col0 >> 1) + wn * 32 + nt * 4 + q;
            g_sc2[(size_t)r * (K_CODES / 2) + c2] =
                __nv_bfloat162(__float2bfloat16_rn(v0), __float2bfloat16_rn(v1));
            g_sc2[(size_t)(r + 8) * (K_CODES / 2) + c2] =
                __nv_bfloat162(__float2bfloat16_rn(v2), __float2bfloat16_rn(v3));
        }
        m1 = fmaxf(m1, __shfl_xor_sync(0xFFFFFFFFu, m1, 1));
        m1 = fmaxf(m1, __shfl_xor_sync(0xFFFFFFFFu, m1, 2));
        m2 = fmaxf(m2, __shfl_xor_sync(0xFFFFFFFFu, m2, 1));
        m2 = fmaxf(m2, __shfl_xor_sync(0xFFFFFFFFu, m2, 2));
        if (q == 0) {
            atomicMax(&g_tilemax[(size_t)r * NTILE + blockIdx.x], fenc(m1));
            atomicMax(&g_tilemax[(size_t)(r + 8) * NTILE + blockIdx.x], fenc(m2));
        }
    }
}

// ---------------------------------------------------------------------------
// Select + gather: warp per row. tilemax -> ballot tiles -> candidate filter
// on surviving tiles -> exact fp32 rescore -> output.
// ---------------------------------------------------------------------------
__global__ __launch_bounds__(256) void select_kernel(const float* __restrict__ x,
                                                     const float* __restrict__ embed,
                                                     float* __restrict__ out, int write_ind) {
    __shared__ int cnt[8];
    __shared__ int cands[8][MAXCAND];

    const int wrow = threadIdx.x >> 5;
    const int row = blockIdx.x * 8 + wrow;
    const int lane = threadIdx.x & 31;
    if (row >= N_ROWS) return;

    // start the longest dependency chain first
    const uint32_t tenc = g_tilemax[(size_t)row * NTILE + lane];

    if (lane == 0) cnt[wrow] = 0;
    __syncwarp();

    const float4* x4 = reinterpret_cast<const float4*>(x + (size_t)row * DDIM);
    float4 xv[4];
#pragma unroll
    for (int j = 0; j < 4; j++) xv[j] = x4[lane + 32 * j];

    const float tv = fdec(tenc);
    float gmax = tv;
#pragma unroll
    for (int off = 16; off; off >>= 1) gmax = fmaxf(gmax, __shfl_xor_sync(0xFFFFFFFFu, gmax, off));

    const float margin = 0.02f * g_xnorm[row] * sqrtf(__int_as_float(g_emax2)) + 1.0f;
    const float thr = gmax - margin;

    unsigned tmask = __ballot_sync(0xFFFFFFFFu, tv >= thr);

    const uint4* s16 = reinterpret_cast<const uint4*>(g_sc2 + (size_t)row * (K_CODES / 2));

    while (tmask) {
        const int t = __ffs(tmask) - 1;
        tmask &= tmask - 1;
        uint4 u = s16[t * 32 + lane];
#pragma unroll
        for (int w = 0; w < 4; w++) {
            uint32_t uw = (&u.x)[w];
            float2 p = __bfloat1622float2(*reinterpret_cast<__nv_bfloat162*>(&uw));
            if (p.x >= thr) {
                int pos = atomicAdd(&cnt[wrow], 1);
                if (pos < MAXCAND) cands[wrow][pos] = t * 256 + lane * 8 + w * 2;
            }
            if (p.y >= thr) {
                int pos = atomicAdd(&cnt[wrow], 1);
                if (pos < MAXCAND) cands[wrow][pos] = t * 256 + lane * 8 + w * 2 + 1;
            }
        }
    }
    __syncwarp();
    const int n = cnt[wrow];

    float best = -CUDART_INF_F;
    int bi = K_CODES;

    if (n <= MAXCAND) {
        for (int ci = 0; ci < n; ci++) {
            int k = cands[wrow][ci];
            const float4* e4 = reinterpret_cast<const float4*>(embed + (size_t)k * DDIM);
            float s = 0.f;
#pragma unroll
            for (int j = 0; j < 4; j++) {
                float4 ev = e4[lane + 32 * j];
                s += xv[j].x * ev.x + xv[j].y * ev.y + xv[j].z * ev.z + xv[j].w * ev.w;
            }
#pragma unroll
            for (int off = 16; off; off >>= 1) s += __shfl_xor_sync(0xFFFFFFFFu, s, off);
            float v = s + g_bias[k];
            if (v > best || (v == best && k < bi)) { best = v; bi = k; }
        }
    } else {
        for (int k = lane; k < K_CODES; k += 32) {
            const float4* e4 = reinterpret_cast<const float4*>(embed + (size_t)k * DDIM);
            float s = 0.f;
            for (int j = 0; j < DDIM / 4; j++) {
                float4 ev = e4[j];
                float4 xw = x4[j];
                s += xw.x * ev.x + xw.y * ev.y + xw.z * ev.z + xw.w * ev.w;
            }
            float v = s + g_bias[k];
            if (v > best || (v == best && k < bi)) { best = v; bi = k; }
        }
#pragma unroll
        for (int off = 16; off; off >>= 1) {
            float ov = __shfl_xor_sync(0xFFFFFFFFu, best, off);
            int   oi = __shfl_xor_sync(0xFFFFFFFFu, bi, off);
            if (ov > best || (ov == best && oi < bi)) { best = ov; bi = oi; }
        }
    }

    bi = __shfl_sync(0xFFFFFFFFu, bi, 0);

    const float4* src = reinterpret_cast<const float4*>(embed + (size_t)bi * DDIM);
    float4* dst = reinterpret_cast<float4*>(out + (size_t)row * DDIM);
#pragma unroll
    for (int j = 0; j < 4; j++) dst[lane + 32 * j] = src[lane + 32 * j];
    if (write_ind && lane == 0) out[(size_t)N_ROWS * DDIM + row] = (float)bi;
}

// ---------------------------------------------------------------------------
extern "C" void kernel_launch(void* const* d_in, const int* in_sizes, int n_in,
                              void* d_out, int out_size) {
    const float* x     = (const float*)d_in[0];
    const float* embed = (const float*)d_in[1];
    float* out = (float*)d_out;
    (void)in_sizes; (void)n_in;
    int write_ind = (out_size >= N_ROWS * DDIM + N_ROWS) ? 1 : 0;

    cudaFuncSetAttribute(gemm_kernel, cudaFuncAttributeMaxDynamicSharedMemorySize, SMEM_GEMM);

    conv_kernel<<<(N_ROWS + K_CODES) / 8, 256>>>(x, embed);
    gemm_kernel<<<dim3(K_CODES / BN, N_ROWS / BM), 256, SMEM_GEMM>>>();
    select_kernel<<<N_ROWS / 8, 256>>>(x, embed, out, write_ind);
}